// round 15
// baseline (speedup 1.0000x reference)
#include <cuda_runtime.h>
#include <cuda_bf16.h>
#include <math.h>
#include <stdint.h>

#define NU_ 100000
#define ND_ 150000
#define NI_ 120000
#define NP_ 80000
#define E_  500000
#define HIDN 128
#define FULLM 0xffffffffu

// ---------------- scratch (static device globals; no allocation) ----------------
__device__ float g_hu[2][(size_t)NU_ * HIDN];
__device__ float g_hd[2][(size_t)ND_ * HIDN];
__device__ float g_hi[2][(size_t)NI_ * HIDN];
__device__ float g_hp[2][(size_t)NP_ * HIDN];
__device__ float g_fs4[4][(size_t)ND_ * HIDN];
__device__ float g_el4[4][ND_ * 4];
__device__ float g_er4[4][ND_ * 4];
__device__ float g_war2[2][4 * 512];
// transposed/split weights: 13 slots x (hi,lo) x 128*128 bf16
__device__ __nv_bfloat16 g_wt[13 * 2 * 16384];
// CSR scratch (4 relations)
__device__ int g_rowptr[4 * ND_];
__device__ int g_deg[4 * ND_];
__device__ int g_csrsrc[4 * E_];
__device__ int g_cursor4[4][ND_];
__device__ int g_bsum4[4][128];

__device__ __forceinline__ float lrelu(float x) { return x > 0.0f ? x : 0.2f * x; }

__device__ __forceinline__ uint32_t smem_u32(const void* p) {
    uint32_t a;
    asm("{ .reg .u64 t; cvta.to.shared.u64 t, %1; cvt.u32.u64 %0, t; }" : "=r"(a) : "l"(p));
    return a;
}

// ================= warp-level MMA helpers =================
__device__ __forceinline__ void ldm_x4(uint32_t* r, uint32_t addr) {
    asm volatile("ldmatrix.sync.aligned.m8n8.x4.shared.b16 {%0,%1,%2,%3}, [%4];"
                 : "=r"(r[0]), "=r"(r[1]), "=r"(r[2]), "=r"(r[3]) : "r"(addr));
}
__device__ __forceinline__ void mma16816(float* d, const uint32_t* a, const uint32_t* b) {
    asm volatile("mma.sync.aligned.m16n8k16.row.col.f32.bf16.bf16.f32 "
                 "{%0,%1,%2,%3}, {%4,%5,%6,%7}, {%8,%9}, {%0,%1,%2,%3};"
                 : "+f"(d[0]), "+f"(d[1]), "+f"(d[2]), "+f"(d[3])
                 : "r"(a[0]), "r"(a[1]), "r"(a[2]), "r"(a[3]), "r"(b[0]), "r"(b[1]));
}

#define A_STRIDE_B 144
#define A_TILE_B (128 * A_STRIDE_B)

// ============== core GEMM body (device inline): C[N,128]=A[N,K]@W + opts ==============
template <int KC>
__device__ __forceinline__ void gemm_body(
    char* sm, const float* __restrict__ A, const __nv_bfloat16* __restrict__ Bhi,
    const __nv_bfloat16* __restrict__ Blo, const float* __restrict__ bias,
    float* __restrict__ C, int Nrows, int act,
    const float* __restrict__ al_vec, float* __restrict__ el_out, int row0)
{
    const int K = KC;
    const int strideB2 = (K + 8) * 2;
    char* p_bhi = sm;
    char* p_blo = sm + 128 * strideB2;
    char* p_a   = sm + 2 * 128 * strideB2;
    const uint32_t s_b_hi = smem_u32(p_bhi);
    const uint32_t s_b_lo = smem_u32(p_blo);
    const uint32_t s_a = smem_u32(p_a);

    const int tid = threadIdx.x;
    const int wid = tid >> 5;
    const int lane = tid & 31;
    const int warp_m = wid & 3;
    const int warp_n = wid >> 2;

    float acc[2][8][4];
#pragma unroll
    for (int m = 0; m < 2; m++)
#pragma unroll
        for (int n = 0; n < 8; n++)
#pragma unroll
            for (int q = 0; q < 4; q++) acc[m][n][q] = 0.0f;

    const int nchunk = K >> 6;
    const int kvs = (K == 128) ? 5 : 4;
    const int kvm = (1 << kvs) - 1;

    // ---- load B fully (hi & lo): K=128 -> 16 iters, K=64 -> 8 ----
    {
        const int niter = (128 << kvs) >> 8;
#pragma unroll
        for (int it = 0; it < 16; it++) {
            if (it >= niter) break;
            int idx = tid + it * 256;
            int row = idx >> kvs;
            int k4 = (idx & kvm) << 2;
            uint2 vh = *(const uint2*)(Bhi + (size_t)row * K + k4);
            uint2 vl = *(const uint2*)(Blo + (size_t)row * K + k4);
            uint32_t off = (uint32_t)row * strideB2 + (uint32_t)k4 * 2;
            *(uint2*)(p_bhi + off) = vh;
            *(uint2*)(p_blo + off) = vl;
        }
    }

    float4 av[8];
    auto loadA = [&](int kc) {
#pragma unroll
        for (int it = 0; it < 8; it++) {
            int idx = tid + it * 256;
            int row = idx >> 4;
            int k4 = (idx & 15) << 2;
            int gr = row0 + row;
            av[it] = make_float4(0.f, 0.f, 0.f, 0.f);
            if (gr < Nrows) av[it] = *(const float4*)(A + (size_t)gr * K + kc * 64 + k4);
        }
    };
    auto storeA = [&](int stg) {
        char* hi = p_a + stg * (2 * A_TILE_B);
        char* lo = hi + A_TILE_B;
#pragma unroll
        for (int it = 0; it < 8; it++) {
            int idx = tid + it * 256;
            int row = idx >> 4;
            int k4 = (idx & 15) << 2;
            float4 v = av[it];
            __nv_bfloat162 h01 = __floats2bfloat162_rn(v.x, v.y);
            __nv_bfloat162 h23 = __floats2bfloat162_rn(v.z, v.w);
            __nv_bfloat162 l01 = __floats2bfloat162_rn(v.x - __bfloat162float(h01.x),
                                                       v.y - __bfloat162float(h01.y));
            __nv_bfloat162 l23 = __floats2bfloat162_rn(v.z - __bfloat162float(h23.x),
                                                       v.w - __bfloat162float(h23.y));
            uint32_t off = (uint32_t)row * A_STRIDE_B + (uint32_t)k4 * 2;
            *(__nv_bfloat162*)(hi + off) = h01;
            *(__nv_bfloat162*)(hi + off + 4) = h23;
            *(__nv_bfloat162*)(lo + off) = l01;
            *(__nv_bfloat162*)(lo + off + 4) = l23;
        }
    };

    loadA(0);
    storeA(0);
    __syncthreads();

    for (int kc = 0; kc < nchunk; kc++) {
        if (kc + 1 < nchunk) loadA(kc + 1);
        const uint32_t a_hi = s_a + (kc & 1) * (2 * A_TILE_B);
        const uint32_t a_lo = a_hi + A_TILE_B;
#pragma unroll
        for (int ks = 0; ks < 4; ks++) {
            const int k0 = ks * 16;
            uint32_t ah[2][4], al_[2][4];
#pragma unroll
            for (int mt = 0; mt < 2; mt++) {
                int r = warp_m * 32 + mt * 16 + (lane & 7) + ((lane >> 3) & 1) * 8;
                int c = k0 + (lane >> 4) * 8;
                uint32_t off = (uint32_t)r * A_STRIDE_B + (uint32_t)c * 2;
                ldm_x4(ah[mt], a_hi + off);
                ldm_x4(al_[mt], a_lo + off);
            }
            uint32_t bh[4][4], bl[4][4];
#pragma unroll
            for (int pp = 0; pp < 4; pp++) {
                int r = warp_n * 64 + pp * 16 + (lane & 7) + (lane >= 16 ? 8 : 0);
                int c = kc * 64 + k0 + ((lane >> 3) & 1) * 8;
                uint32_t off = (uint32_t)r * strideB2 + (uint32_t)c * 2;
                ldm_x4(bh[pp], s_b_hi + off);
                ldm_x4(bl[pp], s_b_lo + off);
            }
#pragma unroll
            for (int mt = 0; mt < 2; mt++)
#pragma unroll
                for (int pp = 0; pp < 4; pp++)
#pragma unroll
                    for (int hh = 0; hh < 2; hh++) {
                        float* d = acc[mt][pp * 2 + hh];
                        mma16816(d, ah[mt], &bh[pp][hh * 2]);
                        mma16816(d, ah[mt], &bl[pp][hh * 2]);
                        mma16816(d, al_[mt], &bh[pp][hh * 2]);
                    }
        }
        if (kc + 1 < nchunk) storeA((kc + 1) & 1);
        __syncthreads();
    }

#pragma unroll
    for (int mt = 0; mt < 2; mt++) {
        int rbase = row0 + warp_m * 32 + mt * 16 + (lane >> 2);
#pragma unroll
        for (int nt = 0; nt < 8; nt++) {
            int col = warp_n * 64 + nt * 8 + (lane & 3) * 2;
            float2 b2 = make_float2(0.f, 0.f);
            if (bias) b2 = *(const float2*)(bias + col);
            float2 o0 = make_float2(acc[mt][nt][0] + b2.x, acc[mt][nt][1] + b2.y);
            float2 o1 = make_float2(acc[mt][nt][2] + b2.x, acc[mt][nt][3] + b2.y);
            if (act == 1) {
                o0.x = fmaxf(o0.x, 0.f); o0.y = fmaxf(o0.y, 0.f);
                o1.x = fmaxf(o1.x, 0.f); o1.y = fmaxf(o1.y, 0.f);
            }
            if (rbase < Nrows)     *(float2*)(C + (size_t)rbase * HIDN + col) = o0;
            if (rbase + 8 < Nrows) *(float2*)(C + (size_t)(rbase + 8) * HIDN + col) = o1;
        }
        if (el_out) {
            float eA0 = 0.f, eA1 = 0.f, eB0 = 0.f, eB1 = 0.f;
#pragma unroll
            for (int nt = 0; nt < 8; nt++) {
                int col = warp_n * 64 + nt * 8 + (lane & 3) * 2;
                float a0 = __ldg(al_vec + col), a1 = __ldg(al_vec + col + 1);
                float p0 = acc[mt][nt][0] * a0 + acc[mt][nt][1] * a1;
                float p1 = acc[mt][nt][2] * a0 + acc[mt][nt][3] * a1;
                if (nt < 4) { eA0 += p0; eA1 += p1; }
                else        { eB0 += p0; eB1 += p1; }
            }
#pragma unroll
            for (int msk = 1; msk <= 2; msk <<= 1) {
                eA0 += __shfl_xor_sync(FULLM, eA0, msk);
                eA1 += __shfl_xor_sync(FULLM, eA1, msk);
                eB0 += __shfl_xor_sync(FULLM, eB0, msk);
                eB1 += __shfl_xor_sync(FULLM, eB1, msk);
            }
            if ((lane & 3) == 0) {
                if (rbase < Nrows)
                    *(float2*)(el_out + (size_t)rbase * 4 + warp_n * 2) = make_float2(eA0, eB0);
                if (rbase + 8 < Nrows)
                    *(float2*)(el_out + (size_t)(rbase + 8) * 4 + warp_n * 2) = make_float2(eA1, eB1);
            }
        }
    }
}

// ---------------- single GEMM (prologue/head) ----------------
__global__ __launch_bounds__(256) void gemm_mma(
    const float* __restrict__ A, const __nv_bfloat16* __restrict__ Bhi,
    const __nv_bfloat16* __restrict__ Blo, const float* __restrict__ bias,
    float* __restrict__ C, int Nrows, int K, int act)
{
    extern __shared__ char sm[];
    if (K == 128)
        gemm_body<128>(sm, A, Bhi, Blo, bias, C, Nrows, act, nullptr, nullptr, blockIdx.x * 128);
    else
        gemm_body<64>(sm, A, Bhi, Blo, bias, C, Nrows, act, nullptr, nullptr, blockIdx.x * 128);
}

// ---------------- batched conv GEMM: blockIdx.y = relation, K=128, fused el ----------------
struct ConvBatch {
    const float* A[4];
    const __nv_bfloat16* Bh[4];
    const __nv_bfloat16* Bl[4];
    float* C[4];
    const float* alv[4];
    float* elo[4];
    int N[4];
};
__global__ __launch_bounds__(256) void gemm_mma_b(ConvBatch gb)
{
    extern __shared__ char sm[];
    int r = blockIdx.y;
    int row0 = blockIdx.x * 128;
    if (row0 >= gb.N[r]) return;
    gemm_body<128>(sm, gb.A[r], gb.Bh[r], gb.Bl[r], nullptr, gb.C[r], gb.N[r], 0,
                   gb.alv[r], gb.elo[r], row0);
}

// ---------------- batched er rowdot (layer 0 only) ----------------
struct RowdotBatch { const float* H[4]; const float* w[4]; float* out[4]; int N[4]; };
__global__ void rowdot_b(RowdotBatch rb)
{
    int r = blockIdx.y;
    __shared__ float ws[512];
    for (int i = threadIdx.x; i < 512; i += blockDim.x) ws[i] = rb.w[r][i];
    __syncthreads();
    int gwarp = (blockIdx.x * blockDim.x + threadIdx.x) >> 5;
    int lane = threadIdx.x & 31;
    if (gwarp >= rb.N[r]) return;
    float4 h = *(const float4*)(rb.H[r] + (size_t)gwarp * HIDN + lane * 4);
    float acc[4] = {0.f, 0.f, 0.f, 0.f};
    const float hv[4] = {h.x, h.y, h.z, h.w};
#pragma unroll
    for (int q = 0; q < 4; q++) {
        int k = lane * 4 + q;
#pragma unroll
        for (int o = 0; o < 4; o++) acc[o] += hv[q] * ws[k * 4 + o];
    }
#pragma unroll
    for (int off = 16; off; off >>= 1)
#pragma unroll
        for (int o = 0; o < 4; o++) acc[o] += __shfl_down_sync(FULLM, acc[o], off);
    if (lane == 0) *(float4*)(rb.out[r] + (size_t)gwarp * 4) = make_float4(acc[0], acc[1], acc[2], acc[3]);
}

// ---------------- plain rowdot (head) ----------------
__global__ void rowdot(const float* __restrict__ Hm, const float* __restrict__ w,
                       const float* __restrict__ bias, float* __restrict__ out,
                       int N, int NOUT)
{
    __shared__ float ws[512];
    for (int i = threadIdx.x; i < 128 * NOUT; i += blockDim.x) ws[i] = w[i];
    __syncthreads();
    int gwarp = (blockIdx.x * blockDim.x + threadIdx.x) >> 5;
    int lane = threadIdx.x & 31;
    if (gwarp >= N) return;
    float4 h = *(const float4*)(Hm + (size_t)gwarp * HIDN + lane * 4);
    float acc[4] = {0.f, 0.f, 0.f, 0.f};
    const float hv[4] = {h.x, h.y, h.z, h.w};
#pragma unroll
    for (int q = 0; q < 4; q++) {
        int k = lane * 4 + q;
        for (int o = 0; o < NOUT; o++) acc[o] += hv[q] * ws[k * NOUT + o];
    }
#pragma unroll
    for (int off = 16; off; off >>= 1)
        for (int o = 0; o < 4; o++) acc[o] += __shfl_down_sync(FULLM, acc[o], off);
    if (lane == 0)
        for (int o = 0; o < NOUT; o++)
            out[(size_t)gwarp * NOUT + o] = acc[o] + (bias ? bias[o] : 0.0f);
}

// ---------------- batched weight convert: blockIdx.y = slot ----------------
struct WBatch { const float* W[13]; int K[13]; };
__global__ void convert_w_b(WBatch wb, __nv_bfloat16* __restrict__ wt)
{
    int s = blockIdx.y;
    int K = wb.K[s];
    int i = blockIdx.x * blockDim.x + threadIdx.x;
    if (i >= 128 * K) return;
    int n = i / K, k = i - n * K;
    float v = wb.W[s][(size_t)k * 128 + n];
    __nv_bfloat16 h = __float2bfloat16(v);
    __nv_bfloat16* hi = wt + (size_t)s * 2 * 16384;
    hi[i] = h;
    hi[16384 + i] = __float2bfloat16(v - __bfloat162float(h));
}

// ---------------- fold ar into W ----------------
__global__ void prep_war(const float* __restrict__ Wc, const float* __restrict__ ar,
                         float* __restrict__ war)
{
    int r = blockIdx.x;
    int k = threadIdx.x;
    const float* W = Wc + (size_t)r * 128 * 128;
    const float* arr = ar + r * 128;
#pragma unroll
    for (int h = 0; h < 4; h++) {
        float sr = 0.f;
#pragma unroll
        for (int d = 0; d < 32; d++) sr += W[k * 128 + h * 32 + d] * arr[h * 32 + d];
        war[r * 512 + k * 4 + h] = sr;
    }
}

// ---------------- batched CSR build ----------------
struct CsrBatch {
    const int* src[4]; const int* dst[4];
    int* deg[4]; int* rp[4]; int* cs[4]; int* cur[4]; int* bs[4];
    int Nd[4];
};
__global__ void zero_deg_b(CsrBatch cb) {
    int r = blockIdx.y;
    int i = blockIdx.x * blockDim.x + threadIdx.x;
    if (i < cb.Nd[r]) cb.deg[r][i] = 0;
}
__global__ void hist_b(CsrBatch cb) {
    int r = blockIdx.y;
    int e = blockIdx.x * blockDim.x + threadIdx.x;
    if (e < E_) atomicAdd(&cb.deg[r][cb.dst[r][e]], 1);
}
#define SCAN_T 256
#define SCAN_E 8
__global__ void scan1_b(CsrBatch cb) {
    int r = blockIdx.y;
    int n = cb.Nd[r];
    const int* in = cb.deg[r];
    int* out = cb.rp[r];
    __shared__ int sm[SCAN_T];
    int base = blockIdx.x * SCAN_T * SCAN_E + threadIdx.x * SCAN_E;
    int v[SCAN_E];
    int s = 0;
#pragma unroll
    for (int i = 0; i < SCAN_E; i++) {
        v[i] = (base + i < n) ? in[base + i] : 0;
        s += v[i];
    }
    sm[threadIdx.x] = s;
    __syncthreads();
    for (int off = 1; off < SCAN_T; off <<= 1) {
        int t = (threadIdx.x >= off) ? sm[threadIdx.x - off] : 0;
        __syncthreads();
        sm[threadIdx.x] += t;
        __syncthreads();
    }
    int run = sm[threadIdx.x] - s;
#pragma unroll
    for (int i = 0; i < SCAN_E; i++) {
        if (base + i < n) out[base + i] = run;
        run += v[i];
    }
    if (threadIdx.x == SCAN_T - 1) cb.bs[r][blockIdx.x] = sm[SCAN_T - 1];
}
__global__ void scan2_b(CsrBatch cb, int nb) {
    int r = blockIdx.x;
    __shared__ int sm[128];
    int v = (threadIdx.x < nb) ? cb.bs[r][threadIdx.x] : 0;
    sm[threadIdx.x] = v;
    __syncthreads();
    for (int off = 1; off < 128; off <<= 1) {
        int t = (threadIdx.x >= off) ? sm[threadIdx.x - off] : 0;
        __syncthreads();
        sm[threadIdx.x] += t;
        __syncthreads();
    }
    if (threadIdx.x < nb) cb.bs[r][threadIdx.x] = sm[threadIdx.x] - v;
}
__global__ void scan3_b(CsrBatch cb) {
    int r = blockIdx.y;
    int i = blockIdx.x * blockDim.x + threadIdx.x;
    if (i < cb.Nd[r]) {
        int v = cb.rp[r][i] + cb.bs[r][i / (SCAN_T * SCAN_E)];
        cb.rp[r][i] = v;
        cb.cur[r][i] = v;
    }
}
__global__ void scatter_b(CsrBatch cb) {
    int r = blockIdx.y;
    int e = blockIdx.x * blockDim.x + threadIdx.x;
    if (e >= E_) return;
    int dn = cb.dst[r][e];
    int pos = atomicAdd(&cb.cur[r][dn], 1);
    cb.cs[r][pos] = cb.src[r][e];
}

// ---------------- FUSED attention: softmax-stats + aggregate + bias + ELU (+er_next) ----------
// warp per dst; flash-style online softmax over CSR neighbors; no eb intermediate.
struct AttnBatch {
    const int* rp[4]; const int* dg[4]; const int* cs[4];
    const float* el[4]; const float* er[4]; const float* fs[4];
    const float* bc;
    float* out[4];
    float* ernext[4];          // null on last layer; else er buffer for next layer (in-place ok)
    const float* warnext[4];   // next layer's folded ar weights [128*4]
    int Nd[4];
};
__global__ void attn_fused_b(AttnBatch ab)
{
    int r = blockIdx.y;
    int gid = blockIdx.x * blockDim.x + threadIdx.x;
    int w = gid >> 5, lane = gid & 31;
    if (w >= ab.Nd[r]) return;
    const int h = lane >> 3;
    int dg = ab.dg[r][w];
    float4 acc = make_float4(0.f, 0.f, 0.f, 0.f);

    if (dg > 0) {
        int st = ab.rp[r][w];
        const int* cs = ab.cs[r];
        const float* el = ab.el[r];
        const float* fs = ab.fs[r];
        float4 er4 = *(const float4*)(ab.er[r] + (size_t)w * 4);

        float m0 = -INFINITY, m1 = -INFINITY, m2 = -INFINITY, m3 = -INFINITY;
        float s0 = 0.f, s1 = 0.f, s2 = 0.f, s3 = 0.f;

        for (int j0 = 0; j0 < dg; j0 += 32) {
            int jj = j0 + lane;
            bool act = jj < dg;
            int sn = act ? __ldg(&cs[st + jj]) : 0;
            float e0, e1, e2, e3;
            if (act) {
                float4 l4 = *(const float4*)(el + (size_t)sn * 4);
                e0 = lrelu(l4.x + er4.x); e1 = lrelu(l4.y + er4.y);
                e2 = lrelu(l4.z + er4.z); e3 = lrelu(l4.w + er4.w);
            } else { e0 = e1 = e2 = e3 = -INFINITY; }

            // chunk max per head (all lanes participate)
            float c0 = e0, c1 = e1, c2 = e2, c3 = e3;
#pragma unroll
            for (int msk = 16; msk; msk >>= 1) {
                c0 = fmaxf(c0, __shfl_xor_sync(FULLM, c0, msk));
                c1 = fmaxf(c1, __shfl_xor_sync(FULLM, c1, msk));
                c2 = fmaxf(c2, __shfl_xor_sync(FULLM, c2, msk));
                c3 = fmaxf(c3, __shfl_xor_sync(FULLM, c3, msk));
            }
            float nm0 = fmaxf(m0, c0), nm1 = fmaxf(m1, c1);
            float nm2 = fmaxf(m2, c2), nm3 = fmaxf(m3, c3);
            float sc0 = __expf(m0 - nm0), sc1 = __expf(m1 - nm1);
            float sc2 = __expf(m2 - nm2), sc3 = __expf(m3 - nm3);

            float x0 = act ? __expf(e0 - nm0) : 0.f;
            float x1 = act ? __expf(e1 - nm1) : 0.f;
            float x2 = act ? __expf(e2 - nm2) : 0.f;
            float x3 = act ? __expf(e3 - nm3) : 0.f;
#pragma unroll
            for (int msk = 16; msk; msk >>= 1) {
                x0 += __shfl_xor_sync(FULLM, x0, msk);
                x1 += __shfl_xor_sync(FULLM, x1, msk);
                x2 += __shfl_xor_sync(FULLM, x2, msk);
                x3 += __shfl_xor_sync(FULLM, x3, msk);
            }
            s0 = s0 * sc0 + x0; s1 = s1 * sc1 + x1;
            s2 = s2 * sc2 + x2; s3 = s3 * sc3 + x3;

            // rescale this lane's accumulator (head = lane>>3)
            float myc = h < 2 ? (h == 0 ? sc0 : sc1) : (h == 2 ? sc2 : sc3);
            acc.x *= myc; acc.y *= myc; acc.z *= myc; acc.w *= myc;
            m0 = nm0; m1 = nm1; m2 = nm2; m3 = nm3;
            float mh = h < 2 ? (h == 0 ? m0 : m1) : (h == 2 ? m2 : m3);

            // accumulate messages for this chunk (serial, 512B coalesced gather each)
            int cnt = dg - j0; if (cnt > 32) cnt = 32;
            for (int t = 0; t < cnt; t++) {
                int snt = __shfl_sync(FULLM, sn, t);
                float et0 = __shfl_sync(FULLM, e0, t);
                float et1 = __shfl_sync(FULLM, e1, t);
                float et2 = __shfl_sync(FULLM, e2, t);
                float et3 = __shfl_sync(FULLM, e3, t);
                float eth = h < 2 ? (h == 0 ? et0 : et1) : (h == 2 ? et2 : et3);
                float a = __expf(eth - mh);
                float4 f = *(const float4*)(fs + (size_t)snt * HIDN + lane * 4);
                acc.x += a * f.x; acc.y += a * f.y;
                acc.z += a * f.z; acc.w += a * f.w;
            }
        }
        float sh = h < 2 ? (h == 0 ? s0 : s1) : (h == 2 ? s2 : s3);
        float inv = 1.0f / sh;
        acc.x *= inv; acc.y *= inv; acc.z *= inv; acc.w *= inv;
    }

    float4 b4 = *(const float4*)(ab.bc + r * 128 + lane * 4);
    acc.x += b4.x; acc.y += b4.y; acc.z += b4.z; acc.w += b4.w;
    acc.x = acc.x > 0.f ? acc.x : expm1f(acc.x);
    acc.y = acc.y > 0.f ? acc.y : expm1f(acc.y);
    acc.z = acc.z > 0.f ? acc.z : expm1f(acc.z);
    acc.w = acc.w > 0.f ? acc.w : expm1f(acc.w);
    *(float4*)(ab.out[r] + (size_t)w * HIDN + lane * 4) = acc;

    // fused er for next layer: er'[w,h'] = sum_k h[k]*war_next[k,h']
    if (ab.ernext[r]) {
        const float* war = ab.warnext[r];
        float p0 = 0.f, p1 = 0.f, p2 = 0.f, p3 = 0.f;
        const float hv[4] = {acc.x, acc.y, acc.z, acc.w};
#pragma unroll
        for (int q = 0; q < 4; q++) {
            float4 wv = *(const float4*)(war + (lane * 4 + q) * 4);
            p0 += hv[q] * wv.x; p1 += hv[q] * wv.y;
            p2 += hv[q] * wv.z; p3 += hv[q] * wv.w;
        }
#pragma unroll
        for (int msk = 16; msk; msk >>= 1) {
            p0 += __shfl_xor_sync(FULLM, p0, msk);
            p1 += __shfl_xor_sync(FULLM, p1, msk);
            p2 += __shfl_xor_sync(FULLM, p2, msk);
            p3 += __shfl_xor_sync(FULLM, p3, msk);
        }
        if (lane == 0)
            *(float4*)(ab.ernext[r] + (size_t)w * 4) = make_float4(p0, p1, p2, p3);
    }
}

// ---------------- host orchestration ----------------
static inline int cdiv(int a, int b) { return (a + b - 1) / b; }

extern "C" void kernel_launch(void* const* d_in, const int* in_sizes, int n_in,
                              void* d_out, int out_size)
{
    (void)in_sizes; (void)n_in; (void)out_size;
    const float* xin[4] = {(const float*)d_in[0], (const float*)d_in[1],
                           (const float*)d_in[2], (const float*)d_in[3]};
    const int* eidx[8];
    for (int i = 0; i < 8; i++) eidx[i] = (const int*)d_in[4 + i];

    const float* Wp[4]  = {(const float*)d_in[12], (const float*)d_in[14],
                           (const float*)d_in[16], (const float*)d_in[18]};
    const float* bpv[4] = {(const float*)d_in[13], (const float*)d_in[15],
                           (const float*)d_in[17], (const float*)d_in[19]};
    const float* Wh1 = (const float*)d_in[28]; const float* bh1 = (const float*)d_in[29];
    const float* Wh2 = (const float*)d_in[30]; const float* bh2 = (const float*)d_in[31];

    void* p;
    cudaGetSymbolAddress(&p, g_hu); float* hu[2] = {(float*)p, (float*)p + (size_t)NU_ * HIDN};
    cudaGetSymbolAddress(&p, g_hd); float* hd[2] = {(float*)p, (float*)p + (size_t)ND_ * HIDN};
    cudaGetSymbolAddress(&p, g_hi); float* hi[2] = {(float*)p, (float*)p + (size_t)NI_ * HIDN};
    cudaGetSymbolAddress(&p, g_hp); float* hp[2] = {(float*)p, (float*)p + (size_t)NP_ * HIDN};
    cudaGetSymbolAddress(&p, g_fs4); float* fs4 = (float*)p;
    cudaGetSymbolAddress(&p, g_el4); float* el4 = (float*)p;
    cudaGetSymbolAddress(&p, g_er4); float* er4 = (float*)p;
    cudaGetSymbolAddress(&p, g_war2); float* war2 = (float*)p;
    cudaGetSymbolAddress(&p, g_wt);  __nv_bfloat16* wt = (__nv_bfloat16*)p;
    cudaGetSymbolAddress(&p, g_rowptr); int* rowptr = (int*)p;
    cudaGetSymbolAddress(&p, g_deg);    int* deg    = (int*)p;
    cudaGetSymbolAddress(&p, g_csrsrc); int* csrsrc = (int*)p;
    cudaGetSymbolAddress(&p, g_cursor4); int* cursor4 = (int*)p;
    cudaGetSymbolAddress(&p, g_bsum4);   int* bsum4   = (int*)p;

    static bool attr_set = false;
    if (!attr_set) {
        cudaFuncSetAttribute(gemm_mma,   cudaFuncAttributeMaxDynamicSharedMemorySize, 144 * 1024);
        cudaFuncSetAttribute(gemm_mma_b, cudaFuncAttributeMaxDynamicSharedMemorySize, 144 * 1024);
        attr_set = true;
    }

    const int Nsrc[4] = {NU_, ND_, NU_, NU_};
    const int Ndst[4] = {ND_, NU_, NI_, NP_};
    const int Nnode[4] = {NU_, ND_, NI_, NP_};
    const int KP[4] = {128, 64, 64, 64};

    auto wslot = [&](int s) { return wt + (size_t)s * 2 * 16384; };
    auto smem_for = [&](int K) { return (size_t)2 * 128 * (K + 8) * 2 + 4 * A_TILE_B; };

    // ---- batched weight conversion (slots 0-3 proj, 4-7 Wc1, 8-11 Wc2, 12 Wh1) ----
    {
        WBatch wb;
        for (int r = 0; r < 4; r++) { wb.W[r] = Wp[r]; wb.K[r] = KP[r]; }
        const float* Wc1 = (const float*)d_in[20];
        const float* Wc2 = (const float*)d_in[24];
        for (int r = 0; r < 4; r++) {
            wb.W[4 + r] = Wc1 + (size_t)r * 16384; wb.K[4 + r] = 128;
            wb.W[8 + r] = Wc2 + (size_t)r * 16384; wb.K[8 + r] = 128;
        }
        wb.W[12] = Wh1; wb.K[12] = 128;
        convert_w_b<<<dim3(64, 13), 256>>>(wb, wt);
    }
    prep_war<<<4, 128>>>((const float*)d_in[20], (const float*)d_in[22], war2);
    prep_war<<<4, 128>>>((const float*)d_in[24], (const float*)d_in[26], war2 + 4 * 512);

    // ---- batched CSR build ----
    CsrBatch cb;
    for (int r = 0; r < 4; r++) {
        cb.src[r] = eidx[2 * r + 0];
        cb.dst[r] = eidx[2 * r + 1];
        cb.deg[r] = deg + (size_t)r * ND_;
        cb.rp[r]  = rowptr + (size_t)r * ND_;
        cb.cs[r]  = csrsrc + (size_t)r * E_;
        cb.cur[r] = cursor4 + (size_t)r * ND_;
        cb.bs[r]  = bsum4 + (size_t)r * 128;
        cb.Nd[r]  = Ndst[r];
    }
    int nb = cdiv(ND_, SCAN_T * SCAN_E);
    zero_deg_b<<<dim3(cdiv(ND_, 256), 4), 256>>>(cb);
    hist_b<<<dim3(cdiv(E_, 256), 4), 256>>>(cb);
    scan1_b<<<dim3(nb, 4), SCAN_T>>>(cb);
    scan2_b<<<4, 128>>>(cb, nb);
    scan3_b<<<dim3(cdiv(ND_, 256), 4), 256>>>(cb);
    scatter_b<<<dim3(cdiv(E_, 256), 4), 256>>>(cb);

    // ---- input projections ----
    for (int r = 0; r < 4; r++) {
        float* dst0 = (r == 0) ? hu[0] : (r == 1) ? hd[0] : (r == 2) ? hi[0] : hp[0];
        gemm_mma<<<cdiv(Nnode[r], 128), 256, smem_for(KP[r])>>>(
            xin[r], wslot(r), wslot(r) + 16384, bpv[r], dst0, Nnode[r], KP[r], 0);
    }

    // ---- layer-0 er from projection outputs (rowdot; later layers fuse into attn) ----
    {
        RowdotBatch rb;
        const float* hdst0[4] = {hd[0], hu[0], hi[0], hp[0]};
        for (int r = 0; r < 4; r++) {
            rb.H[r] = hdst0[r]; rb.w[r] = war2 + r * 512;
            rb.out[r] = er4 + (size_t)r * ND_ * 4; rb.N[r] = Ndst[r];
        }
        rowdot_b<<<dim3(cdiv(ND_, 8), 4), 256>>>(rb);
    }

    // ---- 2 conv layers ----
    const int maxNs = ND_, maxNd = ND_;
    for (int L = 0; L < 2; L++) {
        const float* al = (const float*)d_in[21 + L * 4];
        const float* bc = (const float*)d_in[23 + L * 4];
        int in_b = L & 1, out_b = in_b ^ 1;

        const float* hsrc[4] = {hu[in_b], hd[in_b], hu[in_b], hu[in_b]};
        float* hout[4]       = {hd[out_b], hu[out_b], hi[out_b], hp[out_b]};

        ConvBatch gb;
        AttnBatch ab;
        for (int r = 0; r < 4; r++) {
            float* fs_r = fs4 + (size_t)r * ND_ * HIDN;
            float* el_r = el4 + (size_t)r * ND_ * 4;
            float* er_r = er4 + (size_t)r * ND_ * 4;

            gb.A[r] = hsrc[r];
            gb.Bh[r] = wslot(4 + L * 4 + r); gb.Bl[r] = wslot(4 + L * 4 + r) + 16384;
            gb.C[r] = fs_r; gb.alv[r] = al + r * 128; gb.elo[r] = el_r; gb.N[r] = Nsrc[r];

            ab.rp[r] = cb.rp[r]; ab.dg[r] = cb.deg[r]; ab.cs[r] = cb.cs[r];
            ab.el[r] = el_r; ab.er[r] = er_r; ab.fs[r] = fs_r;
            ab.out[r] = hout[r]; ab.Nd[r] = Ndst[r];
            if (L == 0) {   // write er for layer 1 in-place (safe: 1 warp owns each dst)
                ab.ernext[r] = er_r;
                ab.warnext[r] = war2 + 4 * 512 + r * 512;
            } else {
                ab.ernext[r] = nullptr;
                ab.warnext[r] = nullptr;
            }
        }
        ab.bc = bc;

        gemm_mma_b<<<dim3(cdiv(maxNs, 128), 4), 256, smem_for(128)>>>(gb);
        attn_fused_b<<<dim3(cdiv(maxNd, 8), 4), 256>>>(ab);
    }

    // ---- head ----
    gemm_mma<<<cdiv(NU_, 128), 256, smem_for(128)>>>(
        hu[0], wslot(12), wslot(12) + 16384, bh1, fs4, NU_, 128, 1);
    rowdot<<<cdiv(NU_, 8), 256>>>(fs4, Wh2, bh2, (float*)d_out, NU_, 2);
}

// round 16
// speedup vs baseline: 1.2404x; 1.2404x over previous
#include <cuda_runtime.h>
#include <cuda_bf16.h>
#include <math.h>
#include <stdint.h>

#define NU_ 100000
#define ND_ 150000
#define NI_ 120000
#define NP_ 80000
#define E_  500000
#define HIDN 128
#define FULLM 0xffffffffu

// ---------------- scratch (static device globals; no allocation) ----------------
__device__ float g_hu[2][(size_t)NU_ * HIDN];
__device__ float g_hd[2][(size_t)ND_ * HIDN];
__device__ float g_hi[2][(size_t)NI_ * HIDN];
__device__ float g_hp[2][(size_t)NP_ * HIDN];
__device__ float g_fs4[4][(size_t)ND_ * HIDN];
__device__ float g_eb4[4][(size_t)E_ * 4];
__device__ float g_ms4[4][(size_t)ND_ * 8];   // per-dst m[4], s[4]
__device__ float g_el4[4][ND_ * 4];
__device__ float g_er4[4][ND_ * 4];
__device__ float g_war2[2][4 * 512];
// transposed/split weights: 13 slots x (hi,lo) x 128*128 bf16
__device__ __nv_bfloat16 g_wt[13 * 2 * 16384];
// CSR scratch (4 relations)
__device__ int g_rowptr[4 * ND_];
__device__ int g_deg[4 * ND_];
__device__ int g_csrsrc[4 * E_];
__device__ int g_cursor4[4][ND_];
__device__ int g_bsum4[4][128];

__device__ __forceinline__ float lrelu(float x) { return x > 0.0f ? x : 0.2f * x; }

__device__ __forceinline__ uint32_t smem_u32(const void* p) {
    uint32_t a;
    asm("{ .reg .u64 t; cvta.to.shared.u64 t, %1; cvt.u32.u64 %0, t; }" : "=r"(a) : "l"(p));
    return a;
}

// ================= warp-level MMA helpers =================
__device__ __forceinline__ void ldm_x4(uint32_t* r, uint32_t addr) {
    asm volatile("ldmatrix.sync.aligned.m8n8.x4.shared.b16 {%0,%1,%2,%3}, [%4];"
                 : "=r"(r[0]), "=r"(r[1]), "=r"(r[2]), "=r"(r[3]) : "r"(addr));
}
__device__ __forceinline__ void mma16816(float* d, const uint32_t* a, const uint32_t* b) {
    asm volatile("mma.sync.aligned.m16n8k16.row.col.f32.bf16.bf16.f32 "
                 "{%0,%1,%2,%3}, {%4,%5,%6,%7}, {%8,%9}, {%0,%1,%2,%3};"
                 : "+f"(d[0]), "+f"(d[1]), "+f"(d[2]), "+f"(d[3])
                 : "r"(a[0]), "r"(a[1]), "r"(a[2]), "r"(a[3]), "r"(b[0]), "r"(b[1]));
}

#define A_STRIDE_B 144
#define A_TILE_B (128 * A_STRIDE_B)

// ============== core GEMM body (device inline): C[N,128]=A[N,K]@W + opts ==============
template <int KC>
__device__ __forceinline__ void gemm_body(
    char* sm, const float* __restrict__ A, const __nv_bfloat16* __restrict__ Bhi,
    const __nv_bfloat16* __restrict__ Blo, const float* __restrict__ bias,
    float* __restrict__ C, int Nrows, int act,
    const float* __restrict__ al_vec, float* __restrict__ el_out, int row0)
{
    const int K = KC;
    const int strideB2 = (K + 8) * 2;
    char* p_bhi = sm;
    char* p_blo = sm + 128 * strideB2;
    char* p_a   = sm + 2 * 128 * strideB2;
    const uint32_t s_b_hi = smem_u32(p_bhi);
    const uint32_t s_b_lo = smem_u32(p_blo);
    const uint32_t s_a = smem_u32(p_a);

    const int tid = threadIdx.x;
    const int wid = tid >> 5;
    const int lane = tid & 31;
    const int warp_m = wid & 3;
    const int warp_n = wid >> 2;

    float acc[2][8][4];
#pragma unroll
    for (int m = 0; m < 2; m++)
#pragma unroll
        for (int n = 0; n < 8; n++)
#pragma unroll
            for (int q = 0; q < 4; q++) acc[m][n][q] = 0.0f;

    const int nchunk = K >> 6;
    const int kvs = (K == 128) ? 5 : 4;
    const int kvm = (1 << kvs) - 1;

    // ---- load B fully (hi & lo): K=128 -> 16 iters, K=64 -> 8 ----
    {
        const int niter = (128 << kvs) >> 8;
#pragma unroll
        for (int it = 0; it < 16; it++) {
            if (it >= niter) break;
            int idx = tid + it * 256;
            int row = idx >> kvs;
            int k4 = (idx & kvm) << 2;
            uint2 vh = *(const uint2*)(Bhi + (size_t)row * K + k4);
            uint2 vl = *(const uint2*)(Blo + (size_t)row * K + k4);
            uint32_t off = (uint32_t)row * strideB2 + (uint32_t)k4 * 2;
            *(uint2*)(p_bhi + off) = vh;
            *(uint2*)(p_blo + off) = vl;
        }
    }

    float4 av[8];
    auto loadA = [&](int kc) {
#pragma unroll
        for (int it = 0; it < 8; it++) {
            int idx = tid + it * 256;
            int row = idx >> 4;
            int k4 = (idx & 15) << 2;
            int gr = row0 + row;
            av[it] = make_float4(0.f, 0.f, 0.f, 0.f);
            if (gr < Nrows) av[it] = *(const float4*)(A + (size_t)gr * K + kc * 64 + k4);
        }
    };
    auto storeA = [&](int stg) {
        char* hi = p_a + stg * (2 * A_TILE_B);
        char* lo = hi + A_TILE_B;
#pragma unroll
        for (int it = 0; it < 8; it++) {
            int idx = tid + it * 256;
            int row = idx >> 4;
            int k4 = (idx & 15) << 2;
            float4 v = av[it];
            __nv_bfloat162 h01 = __floats2bfloat162_rn(v.x, v.y);
            __nv_bfloat162 h23 = __floats2bfloat162_rn(v.z, v.w);
            __nv_bfloat162 l01 = __floats2bfloat162_rn(v.x - __bfloat162float(h01.x),
                                                       v.y - __bfloat162float(h01.y));
            __nv_bfloat162 l23 = __floats2bfloat162_rn(v.z - __bfloat162float(h23.x),
                                                       v.w - __bfloat162float(h23.y));
            uint32_t off = (uint32_t)row * A_STRIDE_B + (uint32_t)k4 * 2;
            *(__nv_bfloat162*)(hi + off) = h01;
            *(__nv_bfloat162*)(hi + off + 4) = h23;
            *(__nv_bfloat162*)(lo + off) = l01;
            *(__nv_bfloat162*)(lo + off + 4) = l23;
        }
    };

    loadA(0);
    storeA(0);
    __syncthreads();

    for (int kc = 0; kc < nchunk; kc++) {
        if (kc + 1 < nchunk) loadA(kc + 1);
        const uint32_t a_hi = s_a + (kc & 1) * (2 * A_TILE_B);
        const uint32_t a_lo = a_hi + A_TILE_B;
#pragma unroll
        for (int ks = 0; ks < 4; ks++) {
            const int k0 = ks * 16;
            uint32_t ah[2][4], al_[2][4];
#pragma unroll
            for (int mt = 0; mt < 2; mt++) {
                int r = warp_m * 32 + mt * 16 + (lane & 7) + ((lane >> 3) & 1) * 8;
                int c = k0 + (lane >> 4) * 8;
                uint32_t off = (uint32_t)r * A_STRIDE_B + (uint32_t)c * 2;
                ldm_x4(ah[mt], a_hi + off);
                ldm_x4(al_[mt], a_lo + off);
            }
            uint32_t bh[4][4], bl[4][4];
#pragma unroll
            for (int pp = 0; pp < 4; pp++) {
                int r = warp_n * 64 + pp * 16 + (lane & 7) + (lane >= 16 ? 8 : 0);
                int c = kc * 64 + k0 + ((lane >> 3) & 1) * 8;
                uint32_t off = (uint32_t)r * strideB2 + (uint32_t)c * 2;
                ldm_x4(bh[pp], s_b_hi + off);
                ldm_x4(bl[pp], s_b_lo + off);
            }
#pragma unroll
            for (int mt = 0; mt < 2; mt++)
#pragma unroll
                for (int pp = 0; pp < 4; pp++)
#pragma unroll
                    for (int hh = 0; hh < 2; hh++) {
                        float* d = acc[mt][pp * 2 + hh];
                        mma16816(d, ah[mt], &bh[pp][hh * 2]);
                        mma16816(d, ah[mt], &bl[pp][hh * 2]);
                        mma16816(d, al_[mt], &bh[pp][hh * 2]);
                    }
        }
        if (kc + 1 < nchunk) storeA((kc + 1) & 1);
        __syncthreads();
    }

#pragma unroll
    for (int mt = 0; mt < 2; mt++) {
        int rbase = row0 + warp_m * 32 + mt * 16 + (lane >> 2);
#pragma unroll
        for (int nt = 0; nt < 8; nt++) {
            int col = warp_n * 64 + nt * 8 + (lane & 3) * 2;
            float2 b2 = make_float2(0.f, 0.f);
            if (bias) b2 = *(const float2*)(bias + col);
            float2 o0 = make_float2(acc[mt][nt][0] + b2.x, acc[mt][nt][1] + b2.y);
            float2 o1 = make_float2(acc[mt][nt][2] + b2.x, acc[mt][nt][3] + b2.y);
            if (act == 1) {
                o0.x = fmaxf(o0.x, 0.f); o0.y = fmaxf(o0.y, 0.f);
                o1.x = fmaxf(o1.x, 0.f); o1.y = fmaxf(o1.y, 0.f);
            }
            if (rbase < Nrows)     *(float2*)(C + (size_t)rbase * HIDN + col) = o0;
            if (rbase + 8 < Nrows) *(float2*)(C + (size_t)(rbase + 8) * HIDN + col) = o1;
        }
        if (el_out) {
            float eA0 = 0.f, eA1 = 0.f, eB0 = 0.f, eB1 = 0.f;
#pragma unroll
            for (int nt = 0; nt < 8; nt++) {
                int col = warp_n * 64 + nt * 8 + (lane & 3) * 2;
                float a0 = __ldg(al_vec + col), a1 = __ldg(al_vec + col + 1);
                float p0 = acc[mt][nt][0] * a0 + acc[mt][nt][1] * a1;
                float p1 = acc[mt][nt][2] * a0 + acc[mt][nt][3] * a1;
                if (nt < 4) { eA0 += p0; eA1 += p1; }
                else        { eB0 += p0; eB1 += p1; }
            }
#pragma unroll
            for (int msk = 1; msk <= 2; msk <<= 1) {
                eA0 += __shfl_xor_sync(FULLM, eA0, msk);
                eA1 += __shfl_xor_sync(FULLM, eA1, msk);
                eB0 += __shfl_xor_sync(FULLM, eB0, msk);
                eB1 += __shfl_xor_sync(FULLM, eB1, msk);
            }
            if ((lane & 3) == 0) {
                if (rbase < Nrows)
                    *(float2*)(el_out + (size_t)rbase * 4 + warp_n * 2) = make_float2(eA0, eB0);
                if (rbase + 8 < Nrows)
                    *(float2*)(el_out + (size_t)(rbase + 8) * 4 + warp_n * 2) = make_float2(eA1, eB1);
            }
        }
    }
}

// ---------------- single GEMM (prologue/head) ----------------
__global__ __launch_bounds__(256) void gemm_mma(
    const float* __restrict__ A, const __nv_bfloat16* __restrict__ Bhi,
    const __nv_bfloat16* __restrict__ Blo, const float* __restrict__ bias,
    float* __restrict__ C, int Nrows, int K, int act)
{
    extern __shared__ char sm[];
    if (K == 128)
        gemm_body<128>(sm, A, Bhi, Blo, bias, C, Nrows, act, nullptr, nullptr, blockIdx.x * 128);
    else
        gemm_body<64>(sm, A, Bhi, Blo, bias, C, Nrows, act, nullptr, nullptr, blockIdx.x * 128);
}

// ---------------- batched conv GEMM: blockIdx.y = relation, K=128, fused el ----------------
struct ConvBatch {
    const float* A[4];
    const __nv_bfloat16* Bh[4];
    const __nv_bfloat16* Bl[4];
    float* C[4];
    const float* alv[4];
    float* elo[4];
    int N[4];
};
__global__ __launch_bounds__(256) void gemm_mma_b(ConvBatch gb)
{
    extern __shared__ char sm[];
    int r = blockIdx.y;
    int row0 = blockIdx.x * 128;
    if (row0 >= gb.N[r]) return;
    gemm_body<128>(sm, gb.A[r], gb.Bh[r], gb.Bl[r], nullptr, gb.C[r], gb.N[r], 0,
                   gb.alv[r], gb.elo[r], row0);
}

// ---------------- batched er rowdot (layer 0 only) ----------------
struct RowdotBatch { const float* H[4]; const float* w[4]; float* out[4]; int N[4]; };
__global__ void rowdot_b(RowdotBatch rb)
{
    int r = blockIdx.y;
    __shared__ float ws[512];
    for (int i = threadIdx.x; i < 512; i += blockDim.x) ws[i] = rb.w[r][i];
    __syncthreads();
    int gwarp = (blockIdx.x * blockDim.x + threadIdx.x) >> 5;
    int lane = threadIdx.x & 31;
    if (gwarp >= rb.N[r]) return;
    float4 h = *(const float4*)(rb.H[r] + (size_t)gwarp * HIDN + lane * 4);
    float acc[4] = {0.f, 0.f, 0.f, 0.f};
    const float hv[4] = {h.x, h.y, h.z, h.w};
#pragma unroll
    for (int q = 0; q < 4; q++) {
        int k = lane * 4 + q;
#pragma unroll
        for (int o = 0; o < 4; o++) acc[o] += hv[q] * ws[k * 4 + o];
    }
#pragma unroll
    for (int off = 16; off; off >>= 1)
#pragma unroll
        for (int o = 0; o < 4; o++) acc[o] += __shfl_down_sync(FULLM, acc[o], off);
    if (lane == 0) *(float4*)(rb.out[r] + (size_t)gwarp * 4) = make_float4(acc[0], acc[1], acc[2], acc[3]);
}

// ---------------- plain rowdot (head) ----------------
__global__ void rowdot(const float* __restrict__ Hm, const float* __restrict__ w,
                       const float* __restrict__ bias, float* __restrict__ out,
                       int N, int NOUT)
{
    __shared__ float ws[512];
    for (int i = threadIdx.x; i < 128 * NOUT; i += blockDim.x) ws[i] = w[i];
    __syncthreads();
    int gwarp = (blockIdx.x * blockDim.x + threadIdx.x) >> 5;
    int lane = threadIdx.x & 31;
    if (gwarp >= N) return;
    float4 h = *(const float4*)(Hm + (size_t)gwarp * HIDN + lane * 4);
    float acc[4] = {0.f, 0.f, 0.f, 0.f};
    const float hv[4] = {h.x, h.y, h.z, h.w};
#pragma unroll
    for (int q = 0; q < 4; q++) {
        int k = lane * 4 + q;
        for (int o = 0; o < NOUT; o++) acc[o] += hv[q] * ws[k * NOUT + o];
    }
#pragma unroll
    for (int off = 16; off; off >>= 1)
        for (int o = 0; o < 4; o++) acc[o] += __shfl_down_sync(FULLM, acc[o], off);
    if (lane == 0)
        for (int o = 0; o < NOUT; o++)
            out[(size_t)gwarp * NOUT + o] = acc[o] + (bias ? bias[o] : 0.0f);
}

// ---------------- batched weight convert: blockIdx.y = slot ----------------
struct WBatch { const float* W[13]; int K[13]; };
__global__ void convert_w_b(WBatch wb, __nv_bfloat16* __restrict__ wt)
{
    int s = blockIdx.y;
    int K = wb.K[s];
    int i = blockIdx.x * blockDim.x + threadIdx.x;
    if (i >= 128 * K) return;
    int n = i / K, k = i - n * K;
    float v = wb.W[s][(size_t)k * 128 + n];
    __nv_bfloat16 h = __float2bfloat16(v);
    __nv_bfloat16* hi = wt + (size_t)s * 2 * 16384;
    hi[i] = h;
    hi[16384 + i] = __float2bfloat16(v - __bfloat162float(h));
}

// ---------------- fold ar into W ----------------
__global__ void prep_war(const float* __restrict__ Wc, const float* __restrict__ ar,
                         float* __restrict__ war)
{
    int r = blockIdx.x;
    int k = threadIdx.x;
    const float* W = Wc + (size_t)r * 128 * 128;
    const float* arr = ar + r * 128;
#pragma unroll
    for (int h = 0; h < 4; h++) {
        float sr = 0.f;
#pragma unroll
        for (int d = 0; d < 32; d++) sr += W[k * 128 + h * 32 + d] * arr[h * 32 + d];
        war[r * 512 + k * 4 + h] = sr;
    }
}

// ---------------- batched CSR build ----------------
struct CsrBatch {
    const int* src[4]; const int* dst[4];
    int* deg[4]; int* rp[4]; int* cs[4]; int* cur[4]; int* bs[4];
    int Nd[4];
};
__global__ void zero_deg_b(CsrBatch cb) {
    int r = blockIdx.y;
    int i = blockIdx.x * blockDim.x + threadIdx.x;
    if (i < cb.Nd[r]) cb.deg[r][i] = 0;
}
__global__ void hist_b(CsrBatch cb) {
    int r = blockIdx.y;
    int e = blockIdx.x * blockDim.x + threadIdx.x;
    if (e < E_) atomicAdd(&cb.deg[r][cb.dst[r][e]], 1);
}
#define SCAN_T 256
#define SCAN_E 8
__global__ void scan1_b(CsrBatch cb) {
    int r = blockIdx.y;
    int n = cb.Nd[r];
    const int* in = cb.deg[r];
    int* out = cb.rp[r];
    __shared__ int sm[SCAN_T];
    int base = blockIdx.x * SCAN_T * SCAN_E + threadIdx.x * SCAN_E;
    int v[SCAN_E];
    int s = 0;
#pragma unroll
    for (int i = 0; i < SCAN_E; i++) {
        v[i] = (base + i < n) ? in[base + i] : 0;
        s += v[i];
    }
    sm[threadIdx.x] = s;
    __syncthreads();
    for (int off = 1; off < SCAN_T; off <<= 1) {
        int t = (threadIdx.x >= off) ? sm[threadIdx.x - off] : 0;
        __syncthreads();
        sm[threadIdx.x] += t;
        __syncthreads();
    }
    int run = sm[threadIdx.x] - s;
#pragma unroll
    for (int i = 0; i < SCAN_E; i++) {
        if (base + i < n) out[base + i] = run;
        run += v[i];
    }
    if (threadIdx.x == SCAN_T - 1) cb.bs[r][blockIdx.x] = sm[SCAN_T - 1];
}
__global__ void scan2_b(CsrBatch cb, int nb) {
    int r = blockIdx.x;
    __shared__ int sm[128];
    int v = (threadIdx.x < nb) ? cb.bs[r][threadIdx.x] : 0;
    sm[threadIdx.x] = v;
    __syncthreads();
    for (int off = 1; off < 128; off <<= 1) {
        int t = (threadIdx.x >= off) ? sm[threadIdx.x - off] : 0;
        __syncthreads();
        sm[threadIdx.x] += t;
        __syncthreads();
    }
    if (threadIdx.x < nb) cb.bs[r][threadIdx.x] = sm[threadIdx.x] - v;
}
__global__ void scan3_b(CsrBatch cb) {
    int r = blockIdx.y;
    int i = blockIdx.x * blockDim.x + threadIdx.x;
    if (i < cb.Nd[r]) {
        int v = cb.rp[r][i] + cb.bs[r][i / (SCAN_T * SCAN_E)];
        cb.rp[r][i] = v;
        cb.cur[r][i] = v;
    }
}
__global__ void scatter_b(CsrBatch cb) {
    int r = blockIdx.y;
    int e = blockIdx.x * blockDim.x + threadIdx.x;
    if (e >= E_) return;
    int dn = cb.dst[r][e];
    int pos = atomicAdd(&cb.cur[r][dn], 1);
    cb.cs[r][pos] = cb.src[r][e];
}

// ---------------- batched attention stats: raw e + per-dst (m, s) only ----------------
struct StatsBatch {
    const int* rp[4]; const int* dg[4]; const int* cs[4];
    const float* el[4]; const float* er[4]; float* eb[4]; float* ms[4];
    int Nd[4];
};
__global__ void attn_stats_b(StatsBatch sb)
{
    int r = blockIdx.y;
    int d = blockIdx.x * blockDim.x + threadIdx.x;
    if (d >= sb.Nd[r]) return;
    int dg = sb.dg[r][d];
    if (dg == 0) return;
    int st = sb.rp[r][d];
    const int* cs = sb.cs[r];
    const float* el = sb.el[r];
    float* eb = sb.eb[r];
    float4 r4 = *(const float4*)(sb.er[r] + (size_t)d * 4);
    float m[4] = {-INFINITY, -INFINITY, -INFINITY, -INFINITY};
    float s[4] = {0.f, 0.f, 0.f, 0.f};
    for (int j = 0; j < dg; j++) {
        int sn = cs[st + j];
        float4 l4 = *(const float4*)(el + (size_t)sn * 4);
        float e[4];
        e[0] = lrelu(l4.x + r4.x); e[1] = lrelu(l4.y + r4.y);
        e[2] = lrelu(l4.z + r4.z); e[3] = lrelu(l4.w + r4.w);
        *(float4*)(eb + (size_t)(st + j) * 4) = make_float4(e[0], e[1], e[2], e[3]);
#pragma unroll
        for (int h = 0; h < 4; h++) {
            if (e[h] > m[h]) { s[h] = s[h] * __expf(m[h] - e[h]) + 1.0f; m[h] = e[h]; }
            else             { s[h] += __expf(e[h] - m[h]); }
        }
    }
    float* mso = sb.ms[r] + (size_t)d * 8;
    *(float4*)(mso)     = make_float4(m[0], m[1], m[2], m[3]);
    *(float4*)(mso + 4) = make_float4(1.0f / s[0], 1.0f / s[1], 1.0f / s[2], 1.0f / s[3]);
}

// ---------------- batched aggregate: exp on the fly + bias + ELU (+er_next fused) ----------
struct AggrBatch {
    const int* rp[4]; const int* dg[4]; const int* cs[4];
    const float* eb[4]; const float* ms[4]; const float* fs[4]; const float* bc;
    float* out[4];
    float* ernext[4];          // null on last layer
    const float* warnext[4];
    int Nd[4];
};
__global__ void attn_aggr_b(AggrBatch ab)
{
    int r = blockIdx.y;
    int gid = blockIdx.x * blockDim.x + threadIdx.x;
    int w = gid >> 5, l = gid & 31;
    if (w >= ab.Nd[r]) return;
    int dg = ab.dg[r][w];
    int h = l >> 3;
    float4 acc = make_float4(0.f, 0.f, 0.f, 0.f);
    if (dg > 0) {
        int st = ab.rp[r][w];
        const int* cs = ab.cs[r];
        const float* eb = ab.eb[r];
        const float* fs = ab.fs[r];
        float mh  = __ldg(ab.ms[r] + (size_t)w * 8 + h);
        float ish = __ldg(ab.ms[r] + (size_t)w * 8 + 4 + h);
        for (int j = 0; j < dg; j++) {
            int sn = __ldg(&cs[st + j]);
            float e = __ldg(&eb[(size_t)(st + j) * 4 + h]);
            float a = __expf(e - mh) * ish;
            float4 f = *(const float4*)(fs + (size_t)sn * HIDN + l * 4);
            acc.x += a * f.x; acc.y += a * f.y;
            acc.z += a * f.z; acc.w += a * f.w;
        }
    }
    float4 b4 = *(const float4*)(ab.bc + r * 128 + l * 4);
    acc.x += b4.x; acc.y += b4.y; acc.z += b4.z; acc.w += b4.w;
    acc.x = acc.x > 0.f ? acc.x : expm1f(acc.x);
    acc.y = acc.y > 0.f ? acc.y : expm1f(acc.y);
    acc.z = acc.z > 0.f ? acc.z : expm1f(acc.z);
    acc.w = acc.w > 0.f ? acc.w : expm1f(acc.w);
    *(float4*)(ab.out[r] + (size_t)w * HIDN + l * 4) = acc;

    // fused er for next layer (cheap epilogue; R15's validated-cheap half)
    if (ab.ernext[r]) {
        const float* war = ab.warnext[r];
        float p0 = 0.f, p1 = 0.f, p2 = 0.f, p3 = 0.f;
        const float hv[4] = {acc.x, acc.y, acc.z, acc.w};
#pragma unroll
        for (int q = 0; q < 4; q++) {
            float4 wv = *(const float4*)(war + (l * 4 + q) * 4);
            p0 += hv[q] * wv.x; p1 += hv[q] * wv.y;
            p2 += hv[q] * wv.z; p3 += hv[q] * wv.w;
        }
#pragma unroll
        for (int msk = 16; msk; msk >>= 1) {
            p0 += __shfl_xor_sync(FULLM, p0, msk);
            p1 += __shfl_xor_sync(FULLM, p1, msk);
            p2 += __shfl_xor_sync(FULLM, p2, msk);
            p3 += __shfl_xor_sync(FULLM, p3, msk);
        }
        if (l == 0)
            *(float4*)(ab.ernext[r] + (size_t)w * 4) = make_float4(p0, p1, p2, p3);
    }
}

// ---------------- host orchestration ----------------
static inline int cdiv(int a, int b) { return (a + b - 1) / b; }

extern "C" void kernel_launch(void* const* d_in, const int* in_sizes, int n_in,
                              void* d_out, int out_size)
{
    (void)in_sizes; (void)n_in; (void)out_size;
    const float* xin[4] = {(const float*)d_in[0], (const float*)d_in[1],
                           (const float*)d_in[2], (const float*)d_in[3]};
    const int* eidx[8];
    for (int i = 0; i < 8; i++) eidx[i] = (const int*)d_in[4 + i];

    const float* Wp[4]  = {(const float*)d_in[12], (const float*)d_in[14],
                           (const float*)d_in[16], (const float*)d_in[18]};
    const float* bpv[4] = {(const float*)d_in[13], (const float*)d_in[15],
                           (const float*)d_in[17], (const float*)d_in[19]};
    const float* Wh1 = (const float*)d_in[28]; const float* bh1 = (const float*)d_in[29];
    const float* Wh2 = (const float*)d_in[30]; const float* bh2 = (const float*)d_in[31];

    void* p;
    cudaGetSymbolAddress(&p, g_hu); float* hu[2] = {(float*)p, (float*)p + (size_t)NU_ * HIDN};
    cudaGetSymbolAddress(&p, g_hd); float* hd[2] = {(float*)p, (float*)p + (size_t)ND_ * HIDN};
    cudaGetSymbolAddress(&p, g_hi); float* hi[2] = {(float*)p, (float*)p + (size_t)NI_ * HIDN};
    cudaGetSymbolAddress(&p, g_hp); float* hp[2] = {(float*)p, (float*)p + (size_t)NP_ * HIDN};
    cudaGetSymbolAddress(&p, g_fs4); float* fs4 = (float*)p;
    cudaGetSymbolAddress(&p, g_eb4); float* eb4 = (float*)p;
    cudaGetSymbolAddress(&p, g_ms4); float* ms4 = (float*)p;
    cudaGetSymbolAddress(&p, g_el4); float* el4 = (float*)p;
    cudaGetSymbolAddress(&p, g_er4); float* er4 = (float*)p;
    cudaGetSymbolAddress(&p, g_war2); float* war2 = (float*)p;
    cudaGetSymbolAddress(&p, g_wt);  __nv_bfloat16* wt = (__nv_bfloat16*)p;
    cudaGetSymbolAddress(&p, g_rowptr); int* rowptr = (int*)p;
    cudaGetSymbolAddress(&p, g_deg);    int* deg    = (int*)p;
    cudaGetSymbolAddress(&p, g_csrsrc); int* csrsrc = (int*)p;
    cudaGetSymbolAddress(&p, g_cursor4); int* cursor4 = (int*)p;
    cudaGetSymbolAddress(&p, g_bsum4);   int* bsum4   = (int*)p;

    static bool attr_set = false;
    if (!attr_set) {
        cudaFuncSetAttribute(gemm_mma,   cudaFuncAttributeMaxDynamicSharedMemorySize, 144 * 1024);
        cudaFuncSetAttribute(gemm_mma_b, cudaFuncAttributeMaxDynamicSharedMemorySize, 144 * 1024);
        attr_set = true;
    }

    const int Nsrc[4] = {NU_, ND_, NU_, NU_};
    const int Ndst[4] = {ND_, NU_, NI_, NP_};
    const int Nnode[4] = {NU_, ND_, NI_, NP_};
    const int KP[4] = {128, 64, 64, 64};

    auto wslot = [&](int s) { return wt + (size_t)s * 2 * 16384; };
    auto smem_for = [&](int K) { return (size_t)2 * 128 * (K + 8) * 2 + 4 * A_TILE_B; };

    // ---- batched weight conversion ----
    {
        WBatch wb;
        for (int r = 0; r < 4; r++) { wb.W[r] = Wp[r]; wb.K[r] = KP[r]; }
        const float* Wc1 = (const float*)d_in[20];
        const float* Wc2 = (const float*)d_in[24];
        for (int r = 0; r < 4; r++) {
            wb.W[4 + r] = Wc1 + (size_t)r * 16384; wb.K[4 + r] = 128;
            wb.W[8 + r] = Wc2 + (size_t)r * 16384; wb.K[8 + r] = 128;
        }
        wb.W[12] = Wh1; wb.K[12] = 128;
        convert_w_b<<<dim3(64, 13), 256>>>(wb, wt);
    }
    prep_war<<<4, 128>>>((const float*)d_in[20], (const float*)d_in[22], war2);
    prep_war<<<4, 128>>>((const float*)d_in[24], (const float*)d_in[26], war2 + 4 * 512);

    // ---- batched CSR build ----
    CsrBatch cb;
    for (int r = 0; r < 4; r++) {
        cb.src[r] = eidx[2 * r + 0];
        cb.dst[r] = eidx[2 * r + 1];
        cb.deg[r] = deg + (size_t)r * ND_;
        cb.rp[r]  = rowptr + (size_t)r * ND_;
        cb.cs[r]  = csrsrc + (size_t)r * E_;
        cb.cur[r] = cursor4 + (size_t)r * ND_;
        cb.bs[r]  = bsum4 + (size_t)r * 128;
        cb.Nd[r]  = Ndst[r];
    }
    int nb = cdiv(ND_, SCAN_T * SCAN_E);
    zero_deg_b<<<dim3(cdiv(ND_, 256), 4), 256>>>(cb);
    hist_b<<<dim3(cdiv(E_, 256), 4), 256>>>(cb);
    scan1_b<<<dim3(nb, 4), SCAN_T>>>(cb);
    scan2_b<<<4, 128>>>(cb, nb);
    scan3_b<<<dim3(cdiv(ND_, 256), 4), 256>>>(cb);
    scatter_b<<<dim3(cdiv(E_, 256), 4), 256>>>(cb);

    // ---- input projections ----
    for (int r = 0; r < 4; r++) {
        float* dst0 = (r == 0) ? hu[0] : (r == 1) ? hd[0] : (r == 2) ? hi[0] : hp[0];
        gemm_mma<<<cdiv(Nnode[r], 128), 256, smem_for(KP[r])>>>(
            xin[r], wslot(r), wslot(r) + 16384, bpv[r], dst0, Nnode[r], KP[r], 0);
    }

    // ---- layer-0 er from projection outputs ----
    {
        RowdotBatch rb;
        const float* hdst0[4] = {hd[0], hu[0], hi[0], hp[0]};
        for (int r = 0; r < 4; r++) {
            rb.H[r] = hdst0[r]; rb.w[r] = war2 + r * 512;
            rb.out[r] = er4 + (size_t)r * ND_ * 4; rb.N[r] = Ndst[r];
        }
        rowdot_b<<<dim3(cdiv(ND_, 8), 4), 256>>>(rb);
    }

    // ---- 2 conv layers ----
    const int maxNs = ND_, maxNd = ND_;
    for (int L = 0; L < 2; L++) {
        const float* al = (const float*)d_in[21 + L * 4];
        const float* bc = (const float*)d_in[23 + L * 4];
        int in_b = L & 1, out_b = in_b ^ 1;

        const float* hsrc[4] = {hu[in_b], hd[in_b], hu[in_b], hu[in_b]};
        float* hout[4]       = {hd[out_b], hu[out_b], hi[out_b], hp[out_b]};

        ConvBatch gb;
        StatsBatch sb;
        AggrBatch ab;
        for (int r = 0; r < 4; r++) {
            float* fs_r = fs4 + (size_t)r * ND_ * HIDN;
            float* eb_r = eb4 + (size_t)r * E_ * 4;
            float* ms_r = ms4 + (size_t)r * ND_ * 8;
            float* el_r = el4 + (size_t)r * ND_ * 4;
            float* er_r = er4 + (size_t)r * ND_ * 4;

            gb.A[r] = hsrc[r];
            gb.Bh[r] = wslot(4 + L * 4 + r); gb.Bl[r] = wslot(4 + L * 4 + r) + 16384;
            gb.C[r] = fs_r; gb.alv[r] = al + r * 128; gb.elo[r] = el_r; gb.N[r] = Nsrc[r];

            sb.rp[r] = cb.rp[r]; sb.dg[r] = cb.deg[r]; sb.cs[r] = cb.cs[r];
            sb.el[r] = el_r; sb.er[r] = er_r; sb.eb[r] = eb_r; sb.ms[r] = ms_r;
            sb.Nd[r] = Ndst[r];

            ab.rp[r] = cb.rp[r]; ab.dg[r] = cb.deg[r]; ab.cs[r] = cb.cs[r];
            ab.eb[r] = eb_r; ab.ms[r] = ms_r; ab.fs[r] = fs_r;
            ab.out[r] = hout[r]; ab.Nd[r] = Ndst[r];
            if (L == 0) {   // stats (only er reader) is done before aggr writes er in-place
                ab.ernext[r] = er_r;
                ab.warnext[r] = war2 + 4 * 512 + r * 512;
            } else {
                ab.ernext[r] = nullptr;
                ab.warnext[r] = nullptr;
            }
        }
        ab.bc = bc;

        gemm_mma_b<<<dim3(cdiv(maxNs, 128), 4), 256, smem_for(128)>>>(gb);
        attn_stats_b<<<dim3(cdiv(maxNd, 256), 4), 256>>>(sb);
        attn_aggr_b<<<dim3(cdiv(maxNd, 8), 4), 256>>>(ab);
    }

    // ---- head ----
    gemm_mma<<<cdiv(NU_, 128), 256, smem_for(128)>>>(
        hu[0], wslot(12), wslot(12) + 16384, bh1, fs4, NU_, 128, 1);
    rowdot<<<cdiv(NU_, 8), 256>>>(fs4, Wh2, bh2, (float*)d_out, NU_, 2);
}

// round 17
// speedup vs baseline: 1.2453x; 1.0040x over previous
#include <cuda_runtime.h>
#include <cuda_bf16.h>
#include <math.h>
#include <stdint.h>

#define NU_ 100000
#define ND_ 150000
#define NI_ 120000
#define NP_ 80000
#define E_  500000
#define HIDN 128
#define FULLM 0xffffffffu

// ---------------- scratch (static device globals; no allocation) ----------------
__device__ float g_hu[2][(size_t)NU_ * HIDN];
__device__ float g_hd[2][(size_t)ND_ * HIDN];
__device__ float g_hi[2][(size_t)NI_ * HIDN];
__device__ float g_hp[2][(size_t)NP_ * HIDN];
__device__ float g_fs4[4][(size_t)ND_ * HIDN];
__device__ float g_eb4[4][(size_t)E_ * 4];
__device__ float g_ms4[4][(size_t)ND_ * 8];   // per-dst m[4], 1/s[4]
__device__ float g_el4[4][ND_ * 4];
__device__ float g_er4[4][ND_ * 4];
__device__ float g_war2[2][4 * 512];
// transposed/split weights: 13 slots x (hi,lo) x 128*128 bf16
__device__ __nv_bfloat16 g_wt[13 * 2 * 16384];
// CSR scratch (4 relations)
__device__ int g_rowptr[4 * ND_];
__device__ int g_deg[4 * ND_];
__device__ int g_csrsrc[4 * E_];
__device__ int g_cursor4[4][ND_];
__device__ int g_bsum4[4][128];

__device__ __forceinline__ float lrelu(float x) { return x > 0.0f ? x : 0.2f * x; }

__device__ __forceinline__ uint32_t smem_u32(const void* p) {
    uint32_t a;
    asm("{ .reg .u64 t; cvta.to.shared.u64 t, %1; cvt.u32.u64 %0, t; }" : "=r"(a) : "l"(p));
    return a;
}

// ================= warp-level MMA helpers =================
__device__ __forceinline__ void ldm_x4(uint32_t* r, uint32_t addr) {
    asm volatile("ldmatrix.sync.aligned.m8n8.x4.shared.b16 {%0,%1,%2,%3}, [%4];"
                 : "=r"(r[0]), "=r"(r[1]), "=r"(r[2]), "=r"(r[3]) : "r"(addr));
}
__device__ __forceinline__ void mma16816(float* d, const uint32_t* a, const uint32_t* b) {
    asm volatile("mma.sync.aligned.m16n8k16.row.col.f32.bf16.bf16.f32 "
                 "{%0,%1,%2,%3}, {%4,%5,%6,%7}, {%8,%9}, {%0,%1,%2,%3};"
                 : "+f"(d[0]), "+f"(d[1]), "+f"(d[2]), "+f"(d[3])
                 : "r"(a[0]), "r"(a[1]), "r"(a[2]), "r"(a[3]), "r"(b[0]), "r"(b[1]));
}

#define A_STRIDE_B 144
#define A_TILE_B (128 * A_STRIDE_B)

// ============== core GEMM body (device inline): C[N,128]=A[N,K]@W + opts ==============
template <int KC>
__device__ __forceinline__ void gemm_body(
    char* sm, const float* __restrict__ A, const __nv_bfloat16* __restrict__ Bhi,
    const __nv_bfloat16* __restrict__ Blo, const float* __restrict__ bias,
    float* __restrict__ C, int Nrows, int act,
    const float* __restrict__ al_vec, float* __restrict__ el_out, int row0)
{
    const int K = KC;
    const int strideB2 = (K + 8) * 2;
    char* p_bhi = sm;
    char* p_blo = sm + 128 * strideB2;
    char* p_a   = sm + 2 * 128 * strideB2;
    const uint32_t s_b_hi = smem_u32(p_bhi);
    const uint32_t s_b_lo = smem_u32(p_blo);
    const uint32_t s_a = smem_u32(p_a);

    const int tid = threadIdx.x;
    const int wid = tid >> 5;
    const int lane = tid & 31;
    const int warp_m = wid & 3;
    const int warp_n = wid >> 2;

    float acc[2][8][4];
#pragma unroll
    for (int m = 0; m < 2; m++)
#pragma unroll
        for (int n = 0; n < 8; n++)
#pragma unroll
            for (int q = 0; q < 4; q++) acc[m][n][q] = 0.0f;

    const int nchunk = K >> 6;
    const int kvs = (K == 128) ? 5 : 4;
    const int kvm = (1 << kvs) - 1;

    // ---- load B fully (hi & lo): K=128 -> 16 iters, K=64 -> 8 ----
    {
        const int niter = (128 << kvs) >> 8;
#pragma unroll
        for (int it = 0; it < 16; it++) {
            if (it >= niter) break;
            int idx = tid + it * 256;
            int row = idx >> kvs;
            int k4 = (idx & kvm) << 2;
            uint2 vh = *(const uint2*)(Bhi + (size_t)row * K + k4);
            uint2 vl = *(const uint2*)(Blo + (size_t)row * K + k4);
            uint32_t off = (uint32_t)row * strideB2 + (uint32_t)k4 * 2;
            *(uint2*)(p_bhi + off) = vh;
            *(uint2*)(p_blo + off) = vl;
        }
    }

    float4 av[8];
    auto loadA = [&](int kc) {
#pragma unroll
        for (int it = 0; it < 8; it++) {
            int idx = tid + it * 256;
            int row = idx >> 4;
            int k4 = (idx & 15) << 2;
            int gr = row0 + row;
            av[it] = make_float4(0.f, 0.f, 0.f, 0.f);
            if (gr < Nrows) av[it] = *(const float4*)(A + (size_t)gr * K + kc * 64 + k4);
        }
    };
    auto storeA = [&](int stg) {
        char* hi = p_a + stg * (2 * A_TILE_B);
        char* lo = hi + A_TILE_B;
#pragma unroll
        for (int it = 0; it < 8; it++) {
            int idx = tid + it * 256;
            int row = idx >> 4;
            int k4 = (idx & 15) << 2;
            float4 v = av[it];
            __nv_bfloat162 h01 = __floats2bfloat162_rn(v.x, v.y);
            __nv_bfloat162 h23 = __floats2bfloat162_rn(v.z, v.w);
            __nv_bfloat162 l01 = __floats2bfloat162_rn(v.x - __bfloat162float(h01.x),
                                                       v.y - __bfloat162float(h01.y));
            __nv_bfloat162 l23 = __floats2bfloat162_rn(v.z - __bfloat162float(h23.x),
                                                       v.w - __bfloat162float(h23.y));
            uint32_t off = (uint32_t)row * A_STRIDE_B + (uint32_t)k4 * 2;
            *(__nv_bfloat162*)(hi + off) = h01;
            *(__nv_bfloat162*)(hi + off + 4) = h23;
            *(__nv_bfloat162*)(lo + off) = l01;
            *(__nv_bfloat162*)(lo + off + 4) = l23;
        }
    };

    loadA(0);
    storeA(0);
    __syncthreads();

    for (int kc = 0; kc < nchunk; kc++) {
        if (kc + 1 < nchunk) loadA(kc + 1);
        const uint32_t a_hi = s_a + (kc & 1) * (2 * A_TILE_B);
        const uint32_t a_lo = a_hi + A_TILE_B;
#pragma unroll
        for (int ks = 0; ks < 4; ks++) {
            const int k0 = ks * 16;
            uint32_t ah[2][4], al_[2][4];
#pragma unroll
            for (int mt = 0; mt < 2; mt++) {
                int r = warp_m * 32 + mt * 16 + (lane & 7) + ((lane >> 3) & 1) * 8;
                int c = k0 + (lane >> 4) * 8;
                uint32_t off = (uint32_t)r * A_STRIDE_B + (uint32_t)c * 2;
                ldm_x4(ah[mt], a_hi + off);
                ldm_x4(al_[mt], a_lo + off);
            }
            uint32_t bh[4][4], bl[4][4];
#pragma unroll
            for (int pp = 0; pp < 4; pp++) {
                int r = warp_n * 64 + pp * 16 + (lane & 7) + (lane >= 16 ? 8 : 0);
                int c = kc * 64 + k0 + ((lane >> 3) & 1) * 8;
                uint32_t off = (uint32_t)r * strideB2 + (uint32_t)c * 2;
                ldm_x4(bh[pp], s_b_hi + off);
                ldm_x4(bl[pp], s_b_lo + off);
            }
#pragma unroll
            for (int mt = 0; mt < 2; mt++)
#pragma unroll
                for (int pp = 0; pp < 4; pp++)
#pragma unroll
                    for (int hh = 0; hh < 2; hh++) {
                        float* d = acc[mt][pp * 2 + hh];
                        mma16816(d, ah[mt], &bh[pp][hh * 2]);
                        mma16816(d, ah[mt], &bl[pp][hh * 2]);
                        mma16816(d, al_[mt], &bh[pp][hh * 2]);
                    }
        }
        if (kc + 1 < nchunk) storeA((kc + 1) & 1);
        __syncthreads();
    }

#pragma unroll
    for (int mt = 0; mt < 2; mt++) {
        int rbase = row0 + warp_m * 32 + mt * 16 + (lane >> 2);
#pragma unroll
        for (int nt = 0; nt < 8; nt++) {
            int col = warp_n * 64 + nt * 8 + (lane & 3) * 2;
            float2 b2 = make_float2(0.f, 0.f);
            if (bias) b2 = *(const float2*)(bias + col);
            float2 o0 = make_float2(acc[mt][nt][0] + b2.x, acc[mt][nt][1] + b2.y);
            float2 o1 = make_float2(acc[mt][nt][2] + b2.x, acc[mt][nt][3] + b2.y);
            if (act == 1) {
                o0.x = fmaxf(o0.x, 0.f); o0.y = fmaxf(o0.y, 0.f);
                o1.x = fmaxf(o1.x, 0.f); o1.y = fmaxf(o1.y, 0.f);
            }
            if (rbase < Nrows)     *(float2*)(C + (size_t)rbase * HIDN + col) = o0;
            if (rbase + 8 < Nrows) *(float2*)(C + (size_t)(rbase + 8) * HIDN + col) = o1;
        }
        if (el_out) {
            float eA0 = 0.f, eA1 = 0.f, eB0 = 0.f, eB1 = 0.f;
#pragma unroll
            for (int nt = 0; nt < 8; nt++) {
                int col = warp_n * 64 + nt * 8 + (lane & 3) * 2;
                float a0 = __ldg(al_vec + col), a1 = __ldg(al_vec + col + 1);
                float p0 = acc[mt][nt][0] * a0 + acc[mt][nt][1] * a1;
                float p1 = acc[mt][nt][2] * a0 + acc[mt][nt][3] * a1;
                if (nt < 4) { eA0 += p0; eA1 += p1; }
                else        { eB0 += p0; eB1 += p1; }
            }
#pragma unroll
            for (int msk = 1; msk <= 2; msk <<= 1) {
                eA0 += __shfl_xor_sync(FULLM, eA0, msk);
                eA1 += __shfl_xor_sync(FULLM, eA1, msk);
                eB0 += __shfl_xor_sync(FULLM, eB0, msk);
                eB1 += __shfl_xor_sync(FULLM, eB1, msk);
            }
            if ((lane & 3) == 0) {
                if (rbase < Nrows)
                    *(float2*)(el_out + (size_t)rbase * 4 + warp_n * 2) = make_float2(eA0, eB0);
                if (rbase + 8 < Nrows)
                    *(float2*)(el_out + (size_t)(rbase + 8) * 4 + warp_n * 2) = make_float2(eA1, eB1);
            }
        }
    }
}

// ---------------- single GEMM (head) ----------------
__global__ __launch_bounds__(256) void gemm_mma(
    const float* __restrict__ A, const __nv_bfloat16* __restrict__ Bhi,
    const __nv_bfloat16* __restrict__ Blo, const float* __restrict__ bias,
    float* __restrict__ C, int Nrows, int K, int act)
{
    extern __shared__ char sm[];
    if (K == 128)
        gemm_body<128>(sm, A, Bhi, Blo, bias, C, Nrows, act, nullptr, nullptr, blockIdx.x * 128);
    else
        gemm_body<64>(sm, A, Bhi, Blo, bias, C, Nrows, act, nullptr, nullptr, blockIdx.x * 128);
}

// ---------------- batched projection GEMM: blockIdx.y = node type, per-type K ----------------
struct ProjBatch {
    const float* A[4];
    const __nv_bfloat16* Bh[4];
    const __nv_bfloat16* Bl[4];
    const float* bias[4];
    float* C[4];
    int N[4]; int K[4];
};
__global__ __launch_bounds__(256) void gemm_proj_b(ProjBatch pb)
{
    extern __shared__ char sm[];
    int r = blockIdx.y;
    int row0 = blockIdx.x * 128;
    if (row0 >= pb.N[r]) return;
    if (pb.K[r] == 128)
        gemm_body<128>(sm, pb.A[r], pb.Bh[r], pb.Bl[r], pb.bias[r], pb.C[r], pb.N[r], 0,
                       nullptr, nullptr, row0);
    else
        gemm_body<64>(sm, pb.A[r], pb.Bh[r], pb.Bl[r], pb.bias[r], pb.C[r], pb.N[r], 0,
                      nullptr, nullptr, row0);
}

// ---------------- batched conv GEMM: blockIdx.y = relation, K=128, fused el ----------------
struct ConvBatch {
    const float* A[4];
    const __nv_bfloat16* Bh[4];
    const __nv_bfloat16* Bl[4];
    float* C[4];
    const float* alv[4];
    float* elo[4];
    int N[4];
};
__global__ __launch_bounds__(256) void gemm_mma_b(ConvBatch gb)
{
    extern __shared__ char sm[];
    int r = blockIdx.y;
    int row0 = blockIdx.x * 128;
    if (row0 >= gb.N[r]) return;
    gemm_body<128>(sm, gb.A[r], gb.Bh[r], gb.Bl[r], nullptr, gb.C[r], gb.N[r], 0,
                   gb.alv[r], gb.elo[r], row0);
}

// ---------------- batched er rowdot (layer 0 only) ----------------
struct RowdotBatch { const float* H[4]; const float* w[4]; float* out[4]; int N[4]; };
__global__ void rowdot_b(RowdotBatch rb)
{
    int r = blockIdx.y;
    __shared__ float ws[512];
    for (int i = threadIdx.x; i < 512; i += blockDim.x) ws[i] = rb.w[r][i];
    __syncthreads();
    int gwarp = (blockIdx.x * blockDim.x + threadIdx.x) >> 5;
    int lane = threadIdx.x & 31;
    if (gwarp >= rb.N[r]) return;
    float4 h = *(const float4*)(rb.H[r] + (size_t)gwarp * HIDN + lane * 4);
    float acc[4] = {0.f, 0.f, 0.f, 0.f};
    const float hv[4] = {h.x, h.y, h.z, h.w};
#pragma unroll
    for (int q = 0; q < 4; q++) {
        int k = lane * 4 + q;
#pragma unroll
        for (int o = 0; o < 4; o++) acc[o] += hv[q] * ws[k * 4 + o];
    }
#pragma unroll
    for (int off = 16; off; off >>= 1)
#pragma unroll
        for (int o = 0; o < 4; o++) acc[o] += __shfl_down_sync(FULLM, acc[o], off);
    if (lane == 0) *(float4*)(rb.out[r] + (size_t)gwarp * 4) = make_float4(acc[0], acc[1], acc[2], acc[3]);
}

// ---------------- plain rowdot (head) ----------------
__global__ void rowdot(const float* __restrict__ Hm, const float* __restrict__ w,
                       const float* __restrict__ bias, float* __restrict__ out,
                       int N, int NOUT)
{
    __shared__ float ws[512];
    for (int i = threadIdx.x; i < 128 * NOUT; i += blockDim.x) ws[i] = w[i];
    __syncthreads();
    int gwarp = (blockIdx.x * blockDim.x + threadIdx.x) >> 5;
    int lane = threadIdx.x & 31;
    if (gwarp >= N) return;
    float4 h = *(const float4*)(Hm + (size_t)gwarp * HIDN + lane * 4);
    float acc[4] = {0.f, 0.f, 0.f, 0.f};
    const float hv[4] = {h.x, h.y, h.z, h.w};
#pragma unroll
    for (int q = 0; q < 4; q++) {
        int k = lane * 4 + q;
        for (int o = 0; o < NOUT; o++) acc[o] += hv[q] * ws[k * NOUT + o];
    }
#pragma unroll
    for (int off = 16; off; off >>= 1)
        for (int o = 0; o < 4; o++) acc[o] += __shfl_down_sync(FULLM, acc[o], off);
    if (lane == 0)
        for (int o = 0; o < NOUT; o++)
            out[(size_t)gwarp * NOUT + o] = acc[o] + (bias ? bias[o] : 0.0f);
}

// ---------------- batched weight convert: blockIdx.y = slot ----------------
struct WBatch { const float* W[13]; int K[13]; };
__global__ void convert_w_b(WBatch wb, __nv_bfloat16* __restrict__ wt)
{
    int s = blockIdx.y;
    int K = wb.K[s];
    int i = blockIdx.x * blockDim.x + threadIdx.x;
    if (i >= 128 * K) return;
    int n = i / K, k = i - n * K;
    float v = wb.W[s][(size_t)k * 128 + n];
    __nv_bfloat16 h = __float2bfloat16(v);
    __nv_bfloat16* hi = wt + (size_t)s * 2 * 16384;
    hi[i] = h;
    hi[16384 + i] = __float2bfloat16(v - __bfloat162float(h));
}

// ---------------- fold ar into W ----------------
__global__ void prep_war(const float* __restrict__ Wc, const float* __restrict__ ar,
                         float* __restrict__ war)
{
    int r = blockIdx.x;
    int k = threadIdx.x;
    const float* W = Wc + (size_t)r * 128 * 128;
    const float* arr = ar + r * 128;
#pragma unroll
    for (int h = 0; h < 4; h++) {
        float sr = 0.f;
#pragma unroll
        for (int d = 0; d < 32; d++) sr += W[k * 128 + h * 32 + d] * arr[h * 32 + d];
        war[r * 512 + k * 4 + h] = sr;
    }
}

// ---------------- batched CSR build ----------------
struct CsrBatch {
    const int* src[4]; const int* dst[4];
    int* deg[4]; int* rp[4]; int* cs[4]; int* cur[4]; int* bs[4];
    int Nd[4];
};
__global__ void zero_deg_b(CsrBatch cb) {
    int r = blockIdx.y;
    int i = blockIdx.x * blockDim.x + threadIdx.x;
    if (i < cb.Nd[r]) cb.deg[r][i] = 0;
}
__global__ void hist_b(CsrBatch cb) {
    int r = blockIdx.y;
    int e = blockIdx.x * blockDim.x + threadIdx.x;
    if (e < E_) atomicAdd(&cb.deg[r][cb.dst[r][e]], 1);
}
#define SCAN_T 256
#define SCAN_E 8
__global__ void scan1_b(CsrBatch cb) {
    int r = blockIdx.y;
    int n = cb.Nd[r];
    const int* in = cb.deg[r];
    int* out = cb.rp[r];
    __shared__ int sm[SCAN_T];
    int base = blockIdx.x * SCAN_T * SCAN_E + threadIdx.x * SCAN_E;
    int v[SCAN_E];
    int s = 0;
#pragma unroll
    for (int i = 0; i < SCAN_E; i++) {
        v[i] = (base + i < n) ? in[base + i] : 0;
        s += v[i];
    }
    sm[threadIdx.x] = s;
    __syncthreads();
    for (int off = 1; off < SCAN_T; off <<= 1) {
        int t = (threadIdx.x >= off) ? sm[threadIdx.x - off] : 0;
        __syncthreads();
        sm[threadIdx.x] += t;
        __syncthreads();
    }
    int run = sm[threadIdx.x] - s;
#pragma unroll
    for (int i = 0; i < SCAN_E; i++) {
        if (base + i < n) out[base + i] = run;
        run += v[i];
    }
    if (threadIdx.x == SCAN_T - 1) cb.bs[r][blockIdx.x] = sm[SCAN_T - 1];
}
__global__ void scan2_b(CsrBatch cb, int nb) {
    int r = blockIdx.x;
    __shared__ int sm[128];
    int v = (threadIdx.x < nb) ? cb.bs[r][threadIdx.x] : 0;
    sm[threadIdx.x] = v;
    __syncthreads();
    for (int off = 1; off < 128; off <<= 1) {
        int t = (threadIdx.x >= off) ? sm[threadIdx.x - off] : 0;
        __syncthreads();
        sm[threadIdx.x] += t;
        __syncthreads();
    }
    if (threadIdx.x < nb) cb.bs[r][threadIdx.x] = sm[threadIdx.x] - v;
}
__global__ void scan3_b(CsrBatch cb) {
    int r = blockIdx.y;
    int i = blockIdx.x * blockDim.x + threadIdx.x;
    if (i < cb.Nd[r]) {
        int v = cb.rp[r][i] + cb.bs[r][i / (SCAN_T * SCAN_E)];
        cb.rp[r][i] = v;
        cb.cur[r][i] = v;
    }
}
__global__ void scatter_b(CsrBatch cb) {
    int r = blockIdx.y;
    int e = blockIdx.x * blockDim.x + threadIdx.x;
    if (e >= E_) return;
    int dn = cb.dst[r][e];
    int pos = atomicAdd(&cb.cur[r][dn], 1);
    cb.cs[r][pos] = cb.src[r][e];
}

// ---------------- batched attention stats: raw e + per-dst (m, 1/s) ----------------
struct StatsBatch {
    const int* rp[4]; const int* dg[4]; const int* cs[4];
    const float* el[4]; const float* er[4]; float* eb[4]; float* ms[4];
    int Nd[4];
};
__global__ void attn_stats_b(StatsBatch sb)
{
    int r = blockIdx.y;
    int d = blockIdx.x * blockDim.x + threadIdx.x;
    if (d >= sb.Nd[r]) return;
    int dg = sb.dg[r][d];
    if (dg == 0) return;
    int st = sb.rp[r][d];
    const int* cs = sb.cs[r];
    const float* el = sb.el[r];
    float* eb = sb.eb[r];
    float4 r4 = *(const float4*)(sb.er[r] + (size_t)d * 4);
    float m[4] = {-INFINITY, -INFINITY, -INFINITY, -INFINITY};
    float s[4] = {0.f, 0.f, 0.f, 0.f};
    for (int j = 0; j < dg; j++) {
        int sn = cs[st + j];
        float4 l4 = *(const float4*)(el + (size_t)sn * 4);
        float e[4];
        e[0] = lrelu(l4.x + r4.x); e[1] = lrelu(l4.y + r4.y);
        e[2] = lrelu(l4.z + r4.z); e[3] = lrelu(l4.w + r4.w);
        *(float4*)(eb + (size_t)(st + j) * 4) = make_float4(e[0], e[1], e[2], e[3]);
#pragma unroll
        for (int h = 0; h < 4; h++) {
            if (e[h] > m[h]) { s[h] = s[h] * __expf(m[h] - e[h]) + 1.0f; m[h] = e[h]; }
            else             { s[h] += __expf(e[h] - m[h]); }
        }
    }
    float* mso = sb.ms[r] + (size_t)d * 8;
    *(float4*)(mso)     = make_float4(m[0], m[1], m[2], m[3]);
    *(float4*)(mso + 4) = make_float4(1.0f / s[0], 1.0f / s[1], 1.0f / s[2], 1.0f / s[3]);
}

// ---------------- batched aggregate: exp on the fly + bias + ELU (+er_next fused) ----------
struct AggrBatch {
    const int* rp[4]; const int* dg[4]; const int* cs[4];
    const float* eb[4]; const float* ms[4]; const float* fs[4]; const float* bc;
    float* out[4];
    float* ernext[4];
    const float* warnext[4];
    int Nd[4];
};
__global__ void attn_aggr_b(AggrBatch ab)
{
    int r = blockIdx.y;
    int gid = blockIdx.x * blockDim.x + threadIdx.x;
    int w = gid >> 5, l = gid & 31;
    if (w >= ab.Nd[r]) return;
    int dg = ab.dg[r][w];
    int h = l >> 3;
    float4 acc = make_float4(0.f, 0.f, 0.f, 0.f);
    if (dg > 0) {
        int st = ab.rp[r][w];
        const int* cs = ab.cs[r];
        const float* eb = ab.eb[r];
        const float* fs = ab.fs[r];
        float mh  = __ldg(ab.ms[r] + (size_t)w * 8 + h);
        float ish = __ldg(ab.ms[r] + (size_t)w * 8 + 4 + h);
        for (int j = 0; j < dg; j++) {
            int sn = __ldg(&cs[st + j]);
            float e = __ldg(&eb[(size_t)(st + j) * 4 + h]);
            float a = __expf(e - mh) * ish;
            float4 f = *(const float4*)(fs + (size_t)sn * HIDN + l * 4);
            acc.x += a * f.x; acc.y += a * f.y;
            acc.z += a * f.z; acc.w += a * f.w;
        }
    }
    float4 b4 = *(const float4*)(ab.bc + r * 128 + l * 4);
    acc.x += b4.x; acc.y += b4.y; acc.z += b4.z; acc.w += b4.w;
    acc.x = acc.x > 0.f ? acc.x : expm1f(acc.x);
    acc.y = acc.y > 0.f ? acc.y : expm1f(acc.y);
    acc.z = acc.z > 0.f ? acc.z : expm1f(acc.z);
    acc.w = acc.w > 0.f ? acc.w : expm1f(acc.w);
    *(float4*)(ab.out[r] + (size_t)w * HIDN + l * 4) = acc;

    if (ab.ernext[r]) {
        const float* war = ab.warnext[r];
        float p0 = 0.f, p1 = 0.f, p2 = 0.f, p3 = 0.f;
        const float hv[4] = {acc.x, acc.y, acc.z, acc.w};
#pragma unroll
        for (int q = 0; q < 4; q++) {
            float4 wv = *(const float4*)(war + (l * 4 + q) * 4);
            p0 += hv[q] * wv.x; p1 += hv[q] * wv.y;
            p2 += hv[q] * wv.z; p3 += hv[q] * wv.w;
        }
#pragma unroll
        for (int msk = 16; msk; msk >>= 1) {
            p0 += __shfl_xor_sync(FULLM, p0, msk);
            p1 += __shfl_xor_sync(FULLM, p1, msk);
            p2 += __shfl_xor_sync(FULLM, p2, msk);
            p3 += __shfl_xor_sync(FULLM, p3, msk);
        }
        if (l == 0)
            *(float4*)(ab.ernext[r] + (size_t)w * 4) = make_float4(p0, p1, p2, p3);
    }
}

// ---------------- host orchestration ----------------
static inline int cdiv(int a, int b) { return (a + b - 1) / b; }

extern "C" void kernel_launch(void* const* d_in, const int* in_sizes, int n_in,
                              void* d_out, int out_size)
{
    (void)in_sizes; (void)n_in; (void)out_size;
    const float* xin[4] = {(const float*)d_in[0], (const float*)d_in[1],
                           (const float*)d_in[2], (const float*)d_in[3]};
    const int* eidx[8];
    for (int i = 0; i < 8; i++) eidx[i] = (const int*)d_in[4 + i];

    const float* Wp[4]  = {(const float*)d_in[12], (const float*)d_in[14],
                           (const float*)d_in[16], (const float*)d_in[18]};
    const float* bpv[4] = {(const float*)d_in[13], (const float*)d_in[15],
                           (const float*)d_in[17], (const float*)d_in[19]};
    const float* Wh1 = (const float*)d_in[28]; const float* bh1 = (const float*)d_in[29];
    const float* Wh2 = (const float*)d_in[30]; const float* bh2 = (const float*)d_in[31];

    void* p;
    cudaGetSymbolAddress(&p, g_hu); float* hu[2] = {(float*)p, (float*)p + (size_t)NU_ * HIDN};
    cudaGetSymbolAddress(&p, g_hd); float* hd[2] = {(float*)p, (float*)p + (size_t)ND_ * HIDN};
    cudaGetSymbolAddress(&p, g_hi); float* hi[2] = {(float*)p, (float*)p + (size_t)NI_ * HIDN};
    cudaGetSymbolAddress(&p, g_hp); float* hp[2] = {(float*)p, (float*)p + (size_t)NP_ * HIDN};
    cudaGetSymbolAddress(&p, g_fs4); float* fs4 = (float*)p;
    cudaGetSymbolAddress(&p, g_eb4); float* eb4 = (float*)p;
    cudaGetSymbolAddress(&p, g_ms4); float* ms4 = (float*)p;
    cudaGetSymbolAddress(&p, g_el4); float* el4 = (float*)p;
    cudaGetSymbolAddress(&p, g_er4); float* er4 = (float*)p;
    cudaGetSymbolAddress(&p, g_war2); float* war2 = (float*)p;
    cudaGetSymbolAddress(&p, g_wt);  __nv_bfloat16* wt = (__nv_bfloat16*)p;
    cudaGetSymbolAddress(&p, g_rowptr); int* rowptr = (int*)p;
    cudaGetSymbolAddress(&p, g_deg);    int* deg    = (int*)p;
    cudaGetSymbolAddress(&p, g_csrsrc); int* csrsrc = (int*)p;
    cudaGetSymbolAddress(&p, g_cursor4); int* cursor4 = (int*)p;
    cudaGetSymbolAddress(&p, g_bsum4);   int* bsum4   = (int*)p;

    static bool attr_set = false;
    if (!attr_set) {
        cudaFuncSetAttribute(gemm_mma,    cudaFuncAttributeMaxDynamicSharedMemorySize, 144 * 1024);
        cudaFuncSetAttribute(gemm_mma_b,  cudaFuncAttributeMaxDynamicSharedMemorySize, 144 * 1024);
        cudaFuncSetAttribute(gemm_proj_b, cudaFuncAttributeMaxDynamicSharedMemorySize, 144 * 1024);
        attr_set = true;
    }

    const int Nsrc[4] = {NU_, ND_, NU_, NU_};
    const int Ndst[4] = {ND_, NU_, NI_, NP_};
    const int Nnode[4] = {NU_, ND_, NI_, NP_};
    const int KP[4] = {128, 64, 64, 64};

    auto wslot = [&](int s) { return wt + (size_t)s * 2 * 16384; };
    auto smem_for = [&](int K) { return (size_t)2 * 128 * (K + 8) * 2 + 4 * A_TILE_B; };

    // ---- launch 1: batched weight conversion ----
    {
        WBatch wb;
        for (int r = 0; r < 4; r++) { wb.W[r] = Wp[r]; wb.K[r] = KP[r]; }
        const float* Wc1 = (const float*)d_in[20];
        const float* Wc2 = (const float*)d_in[24];
        for (int r = 0; r < 4; r++) {
            wb.W[4 + r] = Wc1 + (size_t)r * 16384; wb.K[4 + r] = 128;
            wb.W[8 + r] = Wc2 + (size_t)r * 16384; wb.K[8 + r] = 128;
        }
        wb.W[12] = Wh1; wb.K[12] = 128;
        convert_w_b<<<dim3(64, 13), 256>>>(wb, wt);
    }
    // ---- launches 2-3: fold ar ----
    prep_war<<<4, 128>>>((const float*)d_in[20], (const float*)d_in[22], war2);
    prep_war<<<4, 128>>>((const float*)d_in[24], (const float*)d_in[26], war2 + 4 * 512);

    // ---- launch 4: batched input projections (ncu capture window) ----
    {
        ProjBatch pb;
        float* dst0[4] = {hu[0], hd[0], hi[0], hp[0]};
        for (int r = 0; r < 4; r++) {
            pb.A[r] = xin[r];
            pb.Bh[r] = wslot(r); pb.Bl[r] = wslot(r) + 16384;
            pb.bias[r] = bpv[r]; pb.C[r] = dst0[r];
            pb.N[r] = Nnode[r]; pb.K[r] = KP[r];
        }
        gemm_proj_b<<<dim3(cdiv(ND_, 128), 4), 256, smem_for(128)>>>(pb);
    }

    // ---- batched CSR build ----
    CsrBatch cb;
    for (int r = 0; r < 4; r++) {
        cb.src[r] = eidx[2 * r + 0];
        cb.dst[r] = eidx[2 * r + 1];
        cb.deg[r] = deg + (size_t)r * ND_;
        cb.rp[r]  = rowptr + (size_t)r * ND_;
        cb.cs[r]  = csrsrc + (size_t)r * E_;
        cb.cur[r] = cursor4 + (size_t)r * ND_;
        cb.bs[r]  = bsum4 + (size_t)r * 128;
        cb.Nd[r]  = Ndst[r];
    }
    int nb = cdiv(ND_, SCAN_T * SCAN_E);
    zero_deg_b<<<dim3(cdiv(ND_, 256), 4), 256>>>(cb);
    hist_b<<<dim3(cdiv(E_, 256), 4), 256>>>(cb);
    scan1_b<<<dim3(nb, 4), SCAN_T>>>(cb);
    scan2_b<<<4, 128>>>(cb, nb);
    scan3_b<<<dim3(cdiv(ND_, 256), 4), 256>>>(cb);
    scatter_b<<<dim3(cdiv(E_, 256), 4), 256>>>(cb);

    // ---- layer-0 er from projection outputs ----
    {
        RowdotBatch rb;
        const float* hdst0[4] = {hd[0], hu[0], hi[0], hp[0]};
        for (int r = 0; r < 4; r++) {
            rb.H[r] = hdst0[r]; rb.w[r] = war2 + r * 512;
            rb.out[r] = er4 + (size_t)r * ND_ * 4; rb.N[r] = Ndst[r];
        }
        rowdot_b<<<dim3(cdiv(ND_, 8), 4), 256>>>(rb);
    }

    // ---- 2 conv layers ----
    const int maxNs = ND_, maxNd = ND_;
    for (int L = 0; L < 2; L++) {
        const float* al = (const float*)d_in[21 + L * 4];
        const float* bc = (const float*)d_in[23 + L * 4];
        int in_b = L & 1, out_b = in_b ^ 1;

        const float* hsrc[4] = {hu[in_b], hd[in_b], hu[in_b], hu[in_b]};
        float* hout[4]       = {hd[out_b], hu[out_b], hi[out_b], hp[out_b]};

        ConvBatch gb;
        StatsBatch sb;
        AggrBatch ab;
        for (int r = 0; r < 4; r++) {
            float* fs_r = fs4 + (size_t)r * ND_ * HIDN;
            float* eb_r = eb4 + (size_t)r * E_ * 4;
            float* ms_r = ms4 + (size_t)r * ND_ * 8;
            float* el_r = el4 + (size_t)r * ND_ * 4;
            float* er_r = er4 + (size_t)r * ND_ * 4;

            gb.A[r] = hsrc[r];
            gb.Bh[r] = wslot(4 + L * 4 + r); gb.Bl[r] = wslot(4 + L * 4 + r) + 16384;
            gb.C[r] = fs_r; gb.alv[r] = al + r * 128; gb.elo[r] = el_r; gb.N[r] = Nsrc[r];

            sb.rp[r] = cb.rp[r]; sb.dg[r] = cb.deg[r]; sb.cs[r] = cb.cs[r];
            sb.el[r] = el_r; sb.er[r] = er_r; sb.eb[r] = eb_r; sb.ms[r] = ms_r;
            sb.Nd[r] = Ndst[r];

            ab.rp[r] = cb.rp[r]; ab.dg[r] = cb.deg[r]; ab.cs[r] = cb.cs[r];
            ab.eb[r] = eb_r; ab.ms[r] = ms_r; ab.fs[r] = fs_r;
            ab.out[r] = hout[r]; ab.Nd[r] = Ndst[r];
            if (L == 0) {
                ab.ernext[r] = er_r;
                ab.warnext[r] = war2 + 4 * 512 + r * 512;
            } else {
                ab.ernext[r] = nullptr;
                ab.warnext[r] = nullptr;
            }
        }
        ab.bc = bc;

        gemm_mma_b<<<dim3(cdiv(maxNs, 128), 4), 256, smem_for(128)>>>(gb);
        attn_stats_b<<<dim3(cdiv(maxNd, 256), 4), 256>>>(sb);
        attn_aggr_b<<<dim3(cdiv(maxNd, 8), 4), 256>>>(ab);
    }

    // ---- head ----
    gemm_mma<<<cdiv(NU_, 128), 256, smem_for(128)>>>(
        hu[0], wslot(12), wslot(12) + 16384, bh1, fs4, NU_, 128, 1);
    rowdot<<<cdiv(NU_, 8), 256>>>(fs4, Wh2, bh2, (float*)d_out, NU_, 2);
}